// round 1
// baseline (speedup 1.0000x reference)
#include <cuda_runtime.h>
#include <math.h>

// Problem constants (GATModel_10617159155782)
#define N_NODES 50000
#define E_IN    400000
#define E2      (E_IN + N_NODES)   // edges incl. self loops = 450000
#define HEADS   8
#define CH      64
#define HC      512                 // HEADS*CH
#define F_IN    18
#define OUTD    15

// ---------------- scratch (device globals; allocation-free rule) ----------------
__device__ float    g_h[(size_t)N_NODES * HC];   // post-GEMM features
__device__ float    g_y[(size_t)N_NODES * HC];   // aggregated output / next-layer input
__device__ float    g_as[N_NODES * HEADS];
__device__ float    g_ad[N_NODES * HEADS];
__device__ unsigned g_m[N_NODES * HEADS];        // segment max (monotone uint key)
__device__ float    g_den[N_NODES * HEADS];      // segment sum
__device__ float    g_e[(size_t)E2 * HEADS];     // edge logits -> exp numerators
__device__ int      g_src[E2];
__device__ int      g_dst[E2];
__device__ int      g_is64;

// monotone float->uint key: order-preserving, key(x) > 0 for all finite x,
// so memset-style init of 0 acts as -inf identity for atomicMax.
__device__ __forceinline__ unsigned fkey(float f) {
    unsigned u = __float_as_uint(f);
    return (u & 0x80000000u) ? ~u : (u | 0x80000000u);
}
__device__ __forceinline__ float funkey(unsigned k) {
    unsigned u = (k & 0x80000000u) ? (k ^ 0x80000000u) : ~k;
    return __uint_as_float(u);
}

// ---------------- edge index handling ----------------
__global__ void detect_dtype(const unsigned* e) {
    __shared__ int any;
    if (threadIdx.x == 0) any = 0;
    __syncthreads();
    int nz = 0;
    for (int i = threadIdx.x; i < 2048; i += 256)
        if (e[2 * i + 1] != 0u) nz = 1;          // high word of int64 would be 0
    if (nz) atomicOr(&any, 1);
    __syncthreads();
    if (threadIdx.x == 0) g_is64 = (any == 0);
}

__global__ void convert_edges(const void* ep) {
    int i = blockIdx.x * 256 + threadIdx.x;
    if (i >= E2) return;
    if (i < E_IN) {
        int s, d;
        if (g_is64) {
            const long long* p = (const long long*)ep;
            s = (int)p[i];
            d = (int)p[(size_t)E_IN + i];
        } else {
            const int* p = (const int*)ep;
            s = p[i];
            d = p[E_IN + i];
        }
        g_src[i] = s;
        g_dst[i] = d;
    } else {
        g_src[i] = i - E_IN;   // self loops
        g_dst[i] = i - E_IN;
    }
}

// ---------------- layer 1 GEMM: x[N,18] @ W1[18,512] -> g_h ----------------
#define L1_NODES 16
__global__ void __launch_bounds__(256) l1_gemm(const float* __restrict__ x,
                                               const float* __restrict__ W) {
    __shared__ float Ws[F_IN * HC];        // 9216 floats = 36 KB
    __shared__ float xs[L1_NODES * F_IN];  // 288 floats
    int t = threadIdx.x;
    for (int i = t; i < F_IN * HC / 4; i += 256)
        ((float4*)Ws)[i] = ((const float4*)W)[i];
    int n0   = blockIdx.x * L1_NODES;
    int nmax = min(L1_NODES, N_NODES - n0);
    for (int i = t; i < nmax * F_IN; i += 256)
        xs[i] = x[(size_t)n0 * F_IN + i];
    __syncthreads();
    for (int r = 0; r < L1_NODES * HC; r += 256) {
        int idx = r + t;
        int nl = idx >> 9, j = idx & 511;
        if (nl < nmax) {
            float acc = 0.f;
#pragma unroll
            for (int k = 0; k < F_IN; k++) acc += xs[nl * F_IN + k] * Ws[k * HC + j];
            g_h[(size_t)(n0 + nl) * HC + j] = acc;
        }
    }
}

// ---------------- SGEMM 128x128x8: g_h = g_y @ W (M=N_NODES, K=N=512) ----------------
__global__ void __launch_bounds__(256) sgemm128(const float* __restrict__ B) {
    const int M = N_NODES, K = HC, NN = HC;
    __shared__ float As[8][128];
    __shared__ float Bs[8][128];
    int t    = threadIdx.x;
    int row0 = blockIdx.y * 128;
    int col0 = blockIdx.x * 128;
    int arow = t >> 1, acol = (t & 1) * 4;
    int brow = t >> 5, bcol = (t & 31) * 4;
    int tx = t & 15, ty = t >> 4;

    float acc[8][8];
#pragma unroll
    for (int i = 0; i < 8; i++)
#pragma unroll
        for (int j = 0; j < 8; j++) acc[i][j] = 0.f;

    const float* Aptr = g_y + (size_t)(row0 + arow) * K + acol;
    const float* Bptr = B + (size_t)brow * NN + col0 + bcol;
    bool aval = (row0 + arow) < M;

    for (int k0 = 0; k0 < K; k0 += 8) {
        float4 av = aval ? *(const float4*)Aptr : make_float4(0.f, 0.f, 0.f, 0.f);
        As[acol + 0][arow] = av.x;
        As[acol + 1][arow] = av.y;
        As[acol + 2][arow] = av.z;
        As[acol + 3][arow] = av.w;
        *(float4*)&Bs[brow][bcol] = *(const float4*)Bptr;
        __syncthreads();
#pragma unroll
        for (int k = 0; k < 8; k++) {
            float4 a0 = *(float4*)&As[k][ty * 8];
            float4 a1 = *(float4*)&As[k][ty * 8 + 4];
            float4 b0 = *(float4*)&Bs[k][tx * 8];
            float4 b1 = *(float4*)&Bs[k][tx * 8 + 4];
            float a_[8] = {a0.x, a0.y, a0.z, a0.w, a1.x, a1.y, a1.z, a1.w};
            float b_[8] = {b0.x, b0.y, b0.z, b0.w, b1.x, b1.y, b1.z, b1.w};
#pragma unroll
            for (int i = 0; i < 8; i++)
#pragma unroll
                for (int j = 0; j < 8; j++) acc[i][j] += a_[i] * b_[j];
        }
        __syncthreads();
        Aptr += 8;
        Bptr += (size_t)8 * NN;
    }
#pragma unroll
    for (int i = 0; i < 8; i++) {
        int r = row0 + ty * 8 + i;
        if (r < M) {
            float4 s0 = make_float4(acc[i][0], acc[i][1], acc[i][2], acc[i][3]);
            float4 s1 = make_float4(acc[i][4], acc[i][5], acc[i][6], acc[i][7]);
            *(float4*)(g_h + (size_t)r * NN + col0 + tx * 8)     = s0;
            *(float4*)(g_h + (size_t)r * NN + col0 + tx * 8 + 4) = s1;
        }
    }
}

// ---------------- per-node attention coefficients ----------------
__global__ void __launch_bounds__(256) alpha_kernel(const float* __restrict__ a_src,
                                                    const float* __restrict__ a_dst) {
    int n = blockIdx.x;
    int w = threadIdx.x >> 5, lane = threadIdx.x & 31;
    const float* hp = g_h + (size_t)n * HC + w * CH;
    float h0 = hp[lane], h1 = hp[lane + 32];
    float s = h0 * a_src[w * CH + lane] + h1 * a_src[w * CH + lane + 32];
    float d = h0 * a_dst[w * CH + lane] + h1 * a_dst[w * CH + lane + 32];
#pragma unroll
    for (int o = 16; o; o >>= 1) {
        s += __shfl_down_sync(0xffffffffu, s, o);
        d += __shfl_down_sync(0xffffffffu, d, o);
    }
    if (lane == 0) {
        g_as[n * HEADS + w] = s;
        g_ad[n * HEADS + w] = d;
    }
}

// ---------------- zero y / m / den for this layer ----------------
__global__ void zero_layer() {
    size_t i = (size_t)blockIdx.x * 256 + threadIdx.x;
    if (i < (size_t)N_NODES * HC / 4)
        ((float4*)g_y)[i] = make_float4(0.f, 0.f, 0.f, 0.f);
    if (i < (size_t)N_NODES * HEADS) {
        g_m[i]   = 0u;
        g_den[i] = 0.f;
    }
}

// ---------------- edge pass 1: logits + segment max ----------------
__global__ void edge_logits() {
    int tid = blockIdx.x * 256 + threadIdx.x;
    if (tid >= E2 * HEADS) return;
    int e = tid >> 3, h = tid & 7;
    int s = g_src[e], d = g_dst[e];
    float v = g_as[s * HEADS + h] + g_ad[d * HEADS + h];
    v = v > 0.f ? v : 0.2f * v;        // LeakyReLU(0.2)
    g_e[tid] = v;
    atomicMax(&g_m[d * HEADS + h], fkey(v));
}

// ---------------- edge pass 2: exp + segment sum ----------------
__global__ void edge_exp() {
    int tid = blockIdx.x * 256 + threadIdx.x;
    if (tid >= E2 * HEADS) return;
    int e = tid >> 3, h = tid & 7;
    int d = g_dst[e];
    float m  = funkey(g_m[d * HEADS + h]);
    float ex = __expf(g_e[tid] - m);
    g_e[tid] = ex;
    atomicAdd(&g_den[d * HEADS + h], ex);
}

// ---------------- edge pass 3: weighted aggregation (warp per edge) ----------------
__global__ void __launch_bounds__(256) aggregate() {
    int w    = (blockIdx.x * 256 + threadIdx.x) >> 5;
    int lane = threadIdx.x & 31;
    if (w >= E2) return;
    int s = g_src[w], d = g_dst[w];
    float av = 0.f;
    if (lane < 8)
        av = g_e[(size_t)w * 8 + lane] / (g_den[d * 8 + lane] + 1e-16f);
    const float4* hs = (const float4*)(g_h + (size_t)s * HC);
    float4*       yd = (float4*)(g_y + (size_t)d * HC);
#pragma unroll
    for (int i = 0; i < 4; i++) {
        int v = lane + 32 * i;                       // float4 index 0..127
        float al = __shfl_sync(0xffffffffu, av, v >> 4);  // head = v>>4
        float4 hv = hs[v];
        hv.x *= al; hv.y *= al; hv.z *= al; hv.w *= al;
        atomicAdd(yd + v, hv);                       // sm_90+ vector RED.128
    }
}

// ---------------- bias + ELU (layers 1,2) ----------------
__global__ void bias_elu(const float* __restrict__ b) {
    size_t i = (size_t)blockIdx.x * 256 + threadIdx.x;
    if (i >= (size_t)N_NODES * HC / 4) return;
    float4 v  = ((float4*)g_y)[i];
    float4 bb = ((const float4*)b)[i & 127];
    v.x += bb.x; v.y += bb.y; v.z += bb.z; v.w += bb.w;
    v.x = v.x > 0.f ? v.x : expm1f(v.x);
    v.y = v.y > 0.f ? v.y : expm1f(v.y);
    v.z = v.z > 0.f ? v.z : expm1f(v.z);
    v.w = v.w > 0.f ? v.w : expm1f(v.w);
    ((float4*)g_y)[i] = v;
}

// ---------------- head-mean + bias3 + output projection ----------------
__global__ void __launch_bounds__(64) final_kernel(const float* __restrict__ b3,
                                                   const float* __restrict__ Wo,
                                                   const float* __restrict__ bo,
                                                   float* __restrict__ out) {
    __shared__ float s[CH];
    int n = blockIdx.x, t = threadIdx.x;   // 64 threads
    float acc = 0.f;
#pragma unroll
    for (int h = 0; h < HEADS; h++) acc += g_y[(size_t)n * HC + h * CH + t];
    s[t] = acc * 0.125f + b3[t];
    __syncthreads();
    if (t < OUTD) {
        float o = bo[t];
#pragma unroll
        for (int c = 0; c < CH; c++) o += s[c] * Wo[c * OUTD + t];
        out[n * OUTD + t] = o;
    }
}

// ---------------- launcher ----------------
extern "C" void kernel_launch(void* const* d_in, const int* in_sizes, int n_in,
                              void* d_out, int out_size) {
    const float* x     = (const float*)d_in[0];
    const void*  edges = d_in[1];
    const float* W1   = (const float*)d_in[2];
    const float* a1s  = (const float*)d_in[3];
    const float* a1d  = (const float*)d_in[4];
    const float* b1   = (const float*)d_in[5];
    const float* W2   = (const float*)d_in[6];
    const float* a2s  = (const float*)d_in[7];
    const float* a2d  = (const float*)d_in[8];
    const float* b2   = (const float*)d_in[9];
    const float* W3   = (const float*)d_in[10];
    const float* a3s  = (const float*)d_in[11];
    const float* a3d  = (const float*)d_in[12];
    const float* b3   = (const float*)d_in[13];
    const float* Wo   = (const float*)d_in[14];
    const float* bo   = (const float*)d_in[15];
    float* out = (float*)d_out;

    const int EB = (E2 * HEADS + 255) / 256;   // edge*head blocks
    const int WB = (E2 * 32 + 255) / 256;      // warp-per-edge blocks
    const int ZB = (N_NODES * HC / 4 + 255) / 256;

    detect_dtype<<<1, 256>>>((const unsigned*)edges);
    convert_edges<<<(E2 + 255) / 256, 256>>>(edges);

    // ---- layer 1 ----
    l1_gemm<<<(N_NODES + L1_NODES - 1) / L1_NODES, 256>>>(x, W1);
    alpha_kernel<<<N_NODES, 256>>>(a1s, a1d);
    zero_layer<<<ZB, 256>>>();
    edge_logits<<<EB, 256>>>();
    edge_exp<<<EB, 256>>>();
    aggregate<<<WB, 256>>>();
    bias_elu<<<ZB, 256>>>(b1);

    // ---- layer 2 ----
    sgemm128<<<dim3(HC / 128, (N_NODES + 127) / 128), 256>>>(W2);
    alpha_kernel<<<N_NODES, 256>>>(a2s, a2d);
    zero_layer<<<ZB, 256>>>();
    edge_logits<<<EB, 256>>>();
    edge_exp<<<EB, 256>>>();
    aggregate<<<WB, 256>>>();
    bias_elu<<<ZB, 256>>>(b2);

    // ---- layer 3 ----
    sgemm128<<<dim3(HC / 128, (N_NODES + 127) / 128), 256>>>(W3);
    alpha_kernel<<<N_NODES, 256>>>(a3s, a3d);
    zero_layer<<<ZB, 256>>>();
    edge_logits<<<EB, 256>>>();
    edge_exp<<<EB, 256>>>();
    aggregate<<<WB, 256>>>();
    final_kernel<<<N_NODES, 64>>>(b3, Wo, bo, out);
}

// round 3
// speedup vs baseline: 1.2427x; 1.2427x over previous
#include <cuda_runtime.h>
#include <math.h>

// Problem constants (GATModel_10617159155782)
#define N_NODES 50000
#define E_IN    400000
#define E2      (E_IN + N_NODES)   // edges incl. self loops = 450000
#define HEADS   8
#define CH      64
#define HC      512                 // HEADS*CH
#define F_IN    18
#define OUTD    15

// ---------------- scratch (device globals; allocation-free rule) ----------------
// All kernels reference these directly in device code (NEVER passed from host).
__device__ float g_h[(size_t)N_NODES * HC];   // post-GEMM features
__device__ float g_y[(size_t)N_NODES * HC];   // aggregated output / next-layer input
__device__ float g_as[N_NODES * HEADS];
__device__ float g_ad[N_NODES * HEADS];
__device__ int   g_src[E2];
__device__ int   g_dst[E2];
__device__ int   g_deg[N_NODES];
__device__ int   g_rowptr[N_NODES + 1];
__device__ int   g_cur[N_NODES];
__device__ int   g_csrc[E2];       // CSR-ordered source node per incoming edge
__device__ int   g_is64;

// ---------------- edge index handling ----------------
__global__ void detect_dtype(const unsigned* e) {
    __shared__ int any;
    if (threadIdx.x == 0) any = 0;
    __syncthreads();
    int nz = 0;
    for (int i = threadIdx.x; i < 2048; i += 256)
        if (e[2 * i + 1] != 0u) nz = 1;          // high word of int64 would be 0
    if (nz) atomicOr(&any, 1);
    __syncthreads();
    if (threadIdx.x == 0) g_is64 = (any == 0);
}

__global__ void convert_edges(const void* ep) {
    int i = blockIdx.x * 256 + threadIdx.x;
    if (i >= E2) return;
    int s, d;
    if (i < E_IN) {
        if (g_is64) {
            const long long* p = (const long long*)ep;
            s = (int)p[i];
            d = (int)p[(size_t)E_IN + i];
        } else {
            const int* p = (const int*)ep;
            s = p[i];
            d = p[E_IN + i];
        }
    } else {
        s = i - E_IN;   // self loops
        d = i - E_IN;
    }
    g_src[i] = s;
    g_dst[i] = d;
    atomicAdd(&g_deg[d], 1);
}

__global__ void zero_deg() {
    int i = blockIdx.x * 256 + threadIdx.x;
    if (i < N_NODES) g_deg[i] = 0;
}

// single-block exclusive scan over g_deg -> g_rowptr (+ cursor copy)
__global__ void __launch_bounds__(1024) scan_kernel() {
    __shared__ int ssum[1024];
    const int CHUNK = (N_NODES + 1023) / 1024;   // 49
    int t = threadIdx.x;
    int base = t * CHUNK;
    int sum = 0;
    for (int i = 0; i < CHUNK; i++) {
        int idx = base + i;
        if (idx < N_NODES) sum += g_deg[idx];
    }
    ssum[t] = sum;
    __syncthreads();
    for (int o = 1; o < 1024; o <<= 1) {
        int v = (t >= o) ? ssum[t - o] : 0;
        __syncthreads();
        ssum[t] += v;
        __syncthreads();
    }
    int off = (t == 0) ? 0 : ssum[t - 1];
    for (int i = 0; i < CHUNK; i++) {
        int idx = base + i;
        if (idx < N_NODES) {
            g_rowptr[idx] = off;
            g_cur[idx]    = off;
            off += g_deg[idx];
        }
    }
    if (t == 1023) g_rowptr[N_NODES] = E2;
}

__global__ void scatter_edges() {
    int i = blockIdx.x * 256 + threadIdx.x;
    if (i >= E2) return;
    int p = atomicAdd(&g_cur[g_dst[i]], 1);
    g_csrc[p] = g_src[i];
}

// ---------------- layer 1 GEMM: x[N,18] @ W1[18,512] -> g_h ----------------
#define L1_NODES 16
__global__ void __launch_bounds__(256) l1_gemm(const float* __restrict__ x,
                                               const float* __restrict__ W) {
    __shared__ float Ws[F_IN * HC];        // 9216 floats = 36 KB
    __shared__ float xs[L1_NODES * F_IN];
    int t = threadIdx.x;
    for (int i = t; i < F_IN * HC / 4; i += 256)
        ((float4*)Ws)[i] = ((const float4*)W)[i];
    int n0   = blockIdx.x * L1_NODES;
    int nmax = min(L1_NODES, N_NODES - n0);
    for (int i = t; i < nmax * F_IN; i += 256)
        xs[i] = x[(size_t)n0 * F_IN + i];
    __syncthreads();
    for (int r = 0; r < L1_NODES * HC; r += 256) {
        int idx = r + t;
        int nl = idx >> 9, j = idx & 511;
        if (nl < nmax) {
            float acc = 0.f;
#pragma unroll
            for (int k = 0; k < F_IN; k++) acc += xs[nl * F_IN + k] * Ws[k * HC + j];
            g_h[(size_t)(n0 + nl) * HC + j] = acc;
        }
    }
}

// ---------------- SGEMM 128x128x8 (round-1 proven): g_h = g_y @ W  ----------------
__global__ void __launch_bounds__(256) sgemm128(const float* __restrict__ B) {
    const int M = N_NODES, K = HC, NN = HC;
    __shared__ float As[8][128];
    __shared__ float Bs[8][128];
    int t    = threadIdx.x;
    int row0 = blockIdx.y * 128;
    int col0 = blockIdx.x * 128;
    int arow = t >> 1, acol = (t & 1) * 4;
    int brow = t >> 5, bcol = (t & 31) * 4;
    int tx = t & 15, ty = t >> 4;

    float acc[8][8];
#pragma unroll
    for (int i = 0; i < 8; i++)
#pragma unroll
        for (int j = 0; j < 8; j++) acc[i][j] = 0.f;

    const float* Aptr = g_y + (size_t)(row0 + arow) * K + acol;
    const float* Bptr = B + (size_t)brow * NN + col0 + bcol;
    bool aval = (row0 + arow) < M;

    for (int k0 = 0; k0 < K; k0 += 8) {
        float4 av = aval ? *(const float4*)Aptr : make_float4(0.f, 0.f, 0.f, 0.f);
        As[acol + 0][arow] = av.x;
        As[acol + 1][arow] = av.y;
        As[acol + 2][arow] = av.z;
        As[acol + 3][arow] = av.w;
        *(float4*)&Bs[brow][bcol] = *(const float4*)Bptr;
        __syncthreads();
#pragma unroll
        for (int k = 0; k < 8; k++) {
            float4 a0 = *(float4*)&As[k][ty * 8];
            float4 a1 = *(float4*)&As[k][ty * 8 + 4];
            float4 b0 = *(float4*)&Bs[k][tx * 8];
            float4 b1 = *(float4*)&Bs[k][tx * 8 + 4];
            float a_[8] = {a0.x, a0.y, a0.z, a0.w, a1.x, a1.y, a1.z, a1.w};
            float b_[8] = {b0.x, b0.y, b0.z, b0.w, b1.x, b1.y, b1.z, b1.w};
#pragma unroll
            for (int i = 0; i < 8; i++)
#pragma unroll
                for (int j = 0; j < 8; j++) acc[i][j] += a_[i] * b_[j];
        }
        __syncthreads();
        Aptr += 8;
        Bptr += (size_t)8 * NN;
    }
#pragma unroll
    for (int i = 0; i < 8; i++) {
        int r = row0 + ty * 8 + i;
        if (r < M) {
            float4 s0 = make_float4(acc[i][0], acc[i][1], acc[i][2], acc[i][3]);
            float4 s1 = make_float4(acc[i][4], acc[i][5], acc[i][6], acc[i][7]);
            *(float4*)(g_h + (size_t)r * NN + col0 + tx * 8)     = s0;
            *(float4*)(g_h + (size_t)r * NN + col0 + tx * 8 + 4) = s1;
        }
    }
}

// ---------------- per-node attention coefficients ----------------
__global__ void __launch_bounds__(256) alpha_kernel(const float* __restrict__ a_src,
                                                    const float* __restrict__ a_dst) {
    int n = blockIdx.x;
    int w = threadIdx.x >> 5, lane = threadIdx.x & 31;
    const float* hp = g_h + (size_t)n * HC + w * CH;
    float h0 = hp[lane], h1 = hp[lane + 32];
    float s = h0 * a_src[w * CH + lane] + h1 * a_src[w * CH + lane + 32];
    float d = h0 * a_dst[w * CH + lane] + h1 * a_dst[w * CH + lane + 32];
#pragma unroll
    for (int o = 16; o; o >>= 1) {
        s += __shfl_down_sync(0xffffffffu, s, o);
        d += __shfl_down_sync(0xffffffffu, d, o);
    }
    if (lane == 0) {
        g_as[n * HEADS + w] = s;
        g_ad[n * HEADS + w] = d;
    }
}

// ---------------- CSR aggregation: warp per dst node, softmax local, no atomics ----
// elu: 1 = add bias + ELU (layers 1,2), 0 = plain store (layer 3)
__global__ void __launch_bounds__(256) aggregate_csr(const float* __restrict__ bias,
                                                     int elu) {
    int n    = (blockIdx.x * 256 + threadIdx.x) >> 5;
    int lane = threadIdx.x & 31;
    if (n >= N_NODES) return;
    int rs = g_rowptr[n], re = g_rowptr[n + 1];
    int h  = lane & 7;          // head for the softmax phase
    int eo = lane >> 3;         // edge offset (4 edges per iteration)
    float adv = g_ad[n * 8 + h];

    // pass 1: per-head max over incoming edges
    float m = -1e30f;
    for (int i = rs + eo; i < re; i += 4) {
        int s   = g_csrc[i];
        float l = g_as[s * 8 + h] + adv;
        l = l > 0.f ? l : 0.2f * l;
        m = fmaxf(m, l);
    }
    m = fmaxf(m, __shfl_xor_sync(0xffffffffu, m, 8));
    m = fmaxf(m, __shfl_xor_sync(0xffffffffu, m, 16));

    // pass 2: per-head denominator
    float den = 0.f;
    for (int i = rs + eo; i < re; i += 4) {
        int s   = g_csrc[i];
        float l = g_as[s * 8 + h] + adv;
        l = l > 0.f ? l : 0.2f * l;
        den += __expf(l - m);
    }
    den += __shfl_xor_sync(0xffffffffu, den, 8);
    den += __shfl_xor_sync(0xffffffffu, den, 16);
    float inv = 1.f / (den + 1e-16f);

    // pass 3: weighted gather-accumulate (32 lanes x 4 float4 = 512 floats)
    float4 acc0 = make_float4(0.f, 0.f, 0.f, 0.f);
    float4 acc1 = acc0, acc2 = acc0, acc3 = acc0;
    for (int i = rs; i < re; i++) {
        int s = g_csrc[i];
        float a8 = 0.f;
        if (lane < 8) {
            float l = g_as[s * 8 + lane] + adv;
            l  = l > 0.f ? l : 0.2f * l;
            a8 = __expf(l - m) * inv;
        }
        const float4* hs = (const float4*)(g_h + (size_t)s * HC);
        float al;
        float4 hv;
        al = __shfl_sync(0xffffffffu, a8, (lane +  0) >> 4);
        hv = hs[lane +  0];
        acc0.x += al * hv.x; acc0.y += al * hv.y; acc0.z += al * hv.z; acc0.w += al * hv.w;
        al = __shfl_sync(0xffffffffu, a8, (lane + 32) >> 4);
        hv = hs[lane + 32];
        acc1.x += al * hv.x; acc1.y += al * hv.y; acc1.z += al * hv.z; acc1.w += al * hv.w;
        al = __shfl_sync(0xffffffffu, a8, (lane + 64) >> 4);
        hv = hs[lane + 64];
        acc2.x += al * hv.x; acc2.y += al * hv.y; acc2.z += al * hv.z; acc2.w += al * hv.w;
        al = __shfl_sync(0xffffffffu, a8, (lane + 96) >> 4);
        hv = hs[lane + 96];
        acc3.x += al * hv.x; acc3.y += al * hv.y; acc3.z += al * hv.z; acc3.w += al * hv.w;
    }

    float4* yd = (float4*)(g_y + (size_t)n * HC);
    const float4* b4 = (const float4*)bias;
#pragma unroll
    for (int q = 0; q < 4; q++) {
        float4 o = (q == 0) ? acc0 : (q == 1) ? acc1 : (q == 2) ? acc2 : acc3;
        int v = lane + 32 * q;
        if (elu) {
            float4 bb = b4[v];
            o.x += bb.x; o.y += bb.y; o.z += bb.z; o.w += bb.w;
            o.x = o.x > 0.f ? o.x : expm1f(o.x);
            o.y = o.y > 0.f ? o.y : expm1f(o.y);
            o.z = o.z > 0.f ? o.z : expm1f(o.z);
            o.w = o.w > 0.f ? o.w : expm1f(o.w);
        }
        yd[v] = o;
    }
}

// ---------------- head-mean + bias3 + output projection ----------------
__global__ void __launch_bounds__(64) final_kernel(const float* __restrict__ b3,
                                                   const float* __restrict__ Wo,
                                                   const float* __restrict__ bo,
                                                   float* __restrict__ out) {
    __shared__ float s[CH];
    int n = blockIdx.x, t = threadIdx.x;   // 64 threads
    float acc = 0.f;
#pragma unroll
    for (int h = 0; h < HEADS; h++) acc += g_y[(size_t)n * HC + h * CH + t];
    s[t] = acc * 0.125f + b3[t];
    __syncthreads();
    if (t < OUTD) {
        float o = bo[t];
#pragma unroll
        for (int c = 0; c < CH; c++) o += s[c] * Wo[c * OUTD + t];
        out[n * OUTD + t] = o;
    }
}

// ---------------- launcher ----------------
extern "C" void kernel_launch(void* const* d_in, const int* in_sizes, int n_in,
                              void* d_out, int out_size) {
    const float* x     = (const float*)d_in[0];
    const void*  edges = d_in[1];
    const float* W1  = (const float*)d_in[2];
    const float* a1s = (const float*)d_in[3];
    const float* a1d = (const float*)d_in[4];
    const float* b1  = (const float*)d_in[5];
    const float* W2  = (const float*)d_in[6];
    const float* a2s = (const float*)d_in[7];
    const float* a2d = (const float*)d_in[8];
    const float* b2  = (const float*)d_in[9];
    const float* W3  = (const float*)d_in[10];
    const float* a3s = (const float*)d_in[11];
    const float* a3d = (const float*)d_in[12];
    const float* b3  = (const float*)d_in[13];
    const float* Wo  = (const float*)d_in[14];
    const float* bo  = (const float*)d_in[15];
    float* out = (float*)d_out;

    const int AGB = (N_NODES * 32 + 255) / 256;   // warp-per-node blocks
    const dim3 GG(HC / 128, (N_NODES + 127) / 128);

    // CSR build (once per launch; deterministic)
    detect_dtype<<<1, 256>>>((const unsigned*)edges);
    zero_deg<<<(N_NODES + 255) / 256, 256>>>();
    convert_edges<<<(E2 + 255) / 256, 256>>>(edges);
    scan_kernel<<<1, 1024>>>();
    scatter_edges<<<(E2 + 255) / 256, 256>>>();

    // ---- layer 1 ----
    l1_gemm<<<(N_NODES + L1_NODES - 1) / L1_NODES, 256>>>(x, W1);
    alpha_kernel<<<N_NODES, 256>>>(a1s, a1d);
    aggregate_csr<<<AGB, 256>>>(b1, 1);

    // ---- layer 2 ----  (sgemm reads g_y, writes g_h internally)
    sgemm128<<<GG, 256>>>(W2);
    alpha_kernel<<<N_NODES, 256>>>(a2s, a2d);
    aggregate_csr<<<AGB, 256>>>(b2, 1);

    // ---- layer 3 ----
    sgemm128<<<GG, 256>>>(W3);
    alpha_kernel<<<N_NODES, 256>>>(a3s, a3d);
    aggregate_csr<<<AGB, 256>>>(b3, 0);

    final_kernel<<<N_NODES, 64>>>(b3, Wo, bo, out);
}

// round 4
// speedup vs baseline: 1.5222x; 1.2249x over previous
#include <cuda_runtime.h>
#include <math.h>

// Problem constants (GATModel_10617159155782)
#define N_NODES 50000
#define E_IN    400000
#define E2      (E_IN + N_NODES)   // edges incl. self loops = 450000
#define HEADS   8
#define CH      64
#define HC      512                 // HEADS*CH
#define F_IN    18
#define OUTD    15
#define NBLK    ((N_NODES + 255) / 256)   // 196 scan blocks

// ---------------- scratch (device globals; allocation-free rule) ----------------
// All kernels reference these directly in device code (NEVER passed from host).
__device__ float g_h[(size_t)N_NODES * HC];   // post-GEMM features
__device__ float g_y[(size_t)N_NODES * HC];   // aggregated output / next-layer input
__device__ float g_as[N_NODES * HEADS];
__device__ float g_ad[N_NODES * HEADS];
__device__ int   g_src[E2];
__device__ int   g_dst[E2];
__device__ int   g_deg[N_NODES];
__device__ int   g_rowptr[N_NODES + 1];
__device__ int   g_cur[N_NODES];
__device__ int   g_csrc[E2];       // CSR-ordered source node per incoming edge
__device__ int   g_bsum[256];
__device__ int   g_boff[256];
__device__ int   g_is64;

// ---------------- edge index handling ----------------
__global__ void detect_dtype(const unsigned* e) {
    __shared__ int any;
    if (threadIdx.x == 0) any = 0;
    __syncthreads();
    int nz = 0;
    for (int i = threadIdx.x; i < 2048; i += 256)
        if (e[2 * i + 1] != 0u) nz = 1;          // high word of int64 would be 0
    if (nz) atomicOr(&any, 1);
    __syncthreads();
    if (threadIdx.x == 0) g_is64 = (any == 0);
}

__global__ void convert_edges(const void* ep) {
    int i = blockIdx.x * 256 + threadIdx.x;
    if (i >= E2) return;
    int s, d;
    if (i < E_IN) {
        if (g_is64) {
            const long long* p = (const long long*)ep;
            s = (int)p[i];
            d = (int)p[(size_t)E_IN + i];
        } else {
            const int* p = (const int*)ep;
            s = p[i];
            d = p[E_IN + i];
        }
    } else {
        s = i - E_IN;   // self loops
        d = i - E_IN;
    }
    g_src[i] = s;
    g_dst[i] = d;
    atomicAdd(&g_deg[d], 1);
}

__global__ void zero_deg() {
    int i = blockIdx.x * 256 + threadIdx.x;
    if (i < N_NODES) g_deg[i] = 0;
}

// ---------------- fast 3-kernel scan ----------------
__device__ __forceinline__ int block_scan_256(int v, int t, int* total) {
    // returns exclusive prefix of v over 256 threads; *total = block sum
    __shared__ int ws[8];
    int lane = t & 31, w = t >> 5;
    int x = v;
#pragma unroll
    for (int o = 1; o < 32; o <<= 1) {
        int y = __shfl_up_sync(0xffffffffu, x, o);
        if (lane >= o) x += y;
    }
    if (lane == 31) ws[w] = x;
    __syncthreads();
    if (w == 0 && lane < 8) {
        int s = ws[lane];
#pragma unroll
        for (int o = 1; o < 8; o <<= 1) {
            int y = __shfl_up_sync(0xffu, s, o);
            if (lane >= o) s += y;
        }
        ws[lane] = s;
    }
    __syncthreads();
    int base = (w > 0) ? ws[w - 1] : 0;
    *total = ws[7];
    return base + x - v;
}

__global__ void __launch_bounds__(256) scan_blocks() {
    int b = blockIdx.x, t = threadIdx.x;
    int i = b * 256 + t;
    int v = (i < N_NODES) ? g_deg[i] : 0;
    int total;
    int ex = block_scan_256(v, t, &total);
    if (i < N_NODES) g_rowptr[i] = ex;
    if (t == 0) g_bsum[b] = total;
}

__global__ void __launch_bounds__(256) scan_bsums() {
    int t = threadIdx.x;
    int v = (t < NBLK) ? g_bsum[t] : 0;
    int total;
    int ex = block_scan_256(v, t, &total);
    g_boff[t] = ex;
}

__global__ void __launch_bounds__(256) finalize_rowptr() {
    int i = blockIdx.x * 256 + threadIdx.x;
    if (i < N_NODES) {
        int r = g_rowptr[i] + g_boff[i >> 8];
        g_rowptr[i] = r;
        g_cur[i]    = r;
    }
    if (i == 0) g_rowptr[N_NODES] = E2;
}

__global__ void scatter_edges() {
    int i = blockIdx.x * 256 + threadIdx.x;
    if (i >= E2) return;
    int p = atomicAdd(&g_cur[g_dst[i]], 1);
    g_csrc[p] = g_src[i];
}

// ---------------- layer 1 GEMM: x[N,18] @ W1[18,512] -> g_h ----------------
#define L1_NODES 16
__global__ void __launch_bounds__(256) l1_gemm(const float* __restrict__ x,
                                               const float* __restrict__ W) {
    __shared__ float Ws[F_IN * HC];        // 9216 floats = 36 KB
    __shared__ float xs[L1_NODES * F_IN];
    int t = threadIdx.x;
    for (int i = t; i < F_IN * HC / 4; i += 256)
        ((float4*)Ws)[i] = ((const float4*)W)[i];
    int n0   = blockIdx.x * L1_NODES;
    int nmax = min(L1_NODES, N_NODES - n0);
    for (int i = t; i < nmax * F_IN; i += 256)
        xs[i] = x[(size_t)n0 * F_IN + i];
    __syncthreads();
    for (int r = 0; r < L1_NODES * HC; r += 256) {
        int idx = r + t;
        int nl = idx >> 9, j = idx & 511;
        if (nl < nmax) {
            float acc = 0.f;
#pragma unroll
            for (int k = 0; k < F_IN; k++) acc += xs[nl * F_IN + k] * Ws[k * HC + j];
            g_h[(size_t)(n0 + nl) * HC + j] = acc;
        }
    }
}

// ---------------- 3xTF32 tensor-core GEMM: g_h = g_y @ B  (M=50000,K=N=512) ----
#define KT      32
#define LPAD    132
__device__ __forceinline__ unsigned f2tf32(float f) {
    unsigned r;
    asm("cvt.rna.tf32.f32 %0, %1;" : "=r"(r) : "f"(f));
    return r;
}
__device__ __forceinline__ void mma8(float* c, const unsigned* a, const unsigned* b) {
    asm volatile(
        "mma.sync.aligned.m16n8k8.row.col.f32.tf32.tf32.f32 "
        "{%0,%1,%2,%3}, {%4,%5,%6,%7}, {%8,%9}, {%0,%1,%2,%3};"
        : "+f"(c[0]), "+f"(c[1]), "+f"(c[2]), "+f"(c[3])
        : "r"(a[0]), "r"(a[1]), "r"(a[2]), "r"(a[3]), "r"(b[0]), "r"(b[1]));
}

__global__ void __launch_bounds__(256) mma_gemm(const float* __restrict__ B) {
    const int M = N_NODES, K = HC;
    __shared__ float As[KT][LPAD];   // [k][m]
    __shared__ float Bs[KT][LPAD];   // [k][n]
    int tid  = threadIdx.x;
    int lane = tid & 31, warp = tid >> 5;
    int wm = warp & 1, wn = warp >> 1;           // 2 x 4 warp grid
    int row0 = blockIdx.y * 128, col0 = blockIdx.x * 128;
    int g = lane >> 2, t4 = lane & 3;

    // global load indices
    int arb = tid >> 3;            // A rows arb + 32q
    int ak  = (tid & 7) * 4;       // A k offset (4 contiguous)
    int bkb = tid >> 5;            // B k rows bkb + 8q
    int bc  = (lane) * 4;          // B cols (float4)

    float acc[4][4][4];
#pragma unroll
    for (int i = 0; i < 4; i++)
#pragma unroll
        for (int j = 0; j < 4; j++)
#pragma unroll
            for (int r = 0; r < 4; r++) acc[i][j][r] = 0.f;

    float4 ar[4], br[4];
    // prefetch tile 0
#pragma unroll
    for (int q = 0; q < 4; q++) {
        int row = row0 + arb + 32 * q;
        ar[q] = (row < M) ? *(const float4*)(g_y + (size_t)row * K + ak)
                          : make_float4(0.f, 0.f, 0.f, 0.f);
        br[q] = *(const float4*)(B + (size_t)(bkb + 8 * q) * HC + col0 + bc);
    }

    for (int kt = 0; kt < K / KT; kt++) {
        __syncthreads();
#pragma unroll
        for (int q = 0; q < 4; q++) {
            int m = arb + 32 * q;
            As[ak + 0][m] = ar[q].x;
            As[ak + 1][m] = ar[q].y;
            As[ak + 2][m] = ar[q].z;
            As[ak + 3][m] = ar[q].w;
            *(float4*)&Bs[bkb + 8 * q][bc] = br[q];
        }
        __syncthreads();
        if (kt + 1 < K / KT) {
            int k0 = (kt + 1) * KT;
#pragma unroll
            for (int q = 0; q < 4; q++) {
                int row = row0 + arb + 32 * q;
                ar[q] = (row < M) ? *(const float4*)(g_y + (size_t)row * K + k0 + ak)
                                  : make_float4(0.f, 0.f, 0.f, 0.f);
                br[q] = *(const float4*)(B + (size_t)(k0 + bkb + 8 * q) * HC + col0 + bc);
            }
        }
#pragma unroll
        for (int k8 = 0; k8 < KT / 8; k8++) {
            int kb = k8 * 8;
            unsigned bhi[4][2], blo[4][2];
#pragma unroll
            for (int nj = 0; nj < 4; nj++) {
                int n = wn * 32 + nj * 8 + g;
                float b0 = Bs[kb + t4][n];
                float b1 = Bs[kb + t4 + 4][n];
                bhi[nj][0] = f2tf32(b0);
                bhi[nj][1] = f2tf32(b1);
                blo[nj][0] = f2tf32(b0 - __uint_as_float(bhi[nj][0]));
                blo[nj][1] = f2tf32(b1 - __uint_as_float(bhi[nj][1]));
            }
#pragma unroll
            for (int mi = 0; mi < 4; mi++) {
                int m = wm * 64 + mi * 16 + g;
                float a0 = As[kb + t4][m];
                float a1 = As[kb + t4][m + 8];
                float a2 = As[kb + t4 + 4][m];
                float a3 = As[kb + t4 + 4][m + 8];
                unsigned ahi[4], alo[4];
                ahi[0] = f2tf32(a0); alo[0] = f2tf32(a0 - __uint_as_float(ahi[0]));
                ahi[1] = f2tf32(a1); alo[1] = f2tf32(a1 - __uint_as_float(ahi[1]));
                ahi[2] = f2tf32(a2); alo[2] = f2tf32(a2 - __uint_as_float(ahi[2]));
                ahi[3] = f2tf32(a3); alo[3] = f2tf32(a3 - __uint_as_float(ahi[3]));
#pragma unroll
                for (int nj = 0; nj < 4; nj++) {
                    mma8(acc[mi][nj], ahi, bhi[nj]);
                    mma8(acc[mi][nj], ahi, blo[nj]);
                    mma8(acc[mi][nj], alo, bhi[nj]);
                }
            }
        }
    }

    // epilogue: write C
#pragma unroll
    for (int mi = 0; mi < 4; mi++) {
#pragma unroll
        for (int nj = 0; nj < 4; nj++) {
            int r0 = row0 + wm * 64 + mi * 16 + g;
            int c  = col0 + wn * 32 + nj * 8 + 2 * t4;
            if (r0 < M) {
                float2 v = make_float2(acc[mi][nj][0], acc[mi][nj][1]);
                *(float2*)(g_h + (size_t)r0 * HC + c) = v;
            }
            if (r0 + 8 < M) {
                float2 v = make_float2(acc[mi][nj][2], acc[mi][nj][3]);
                *(float2*)(g_h + (size_t)(r0 + 8) * HC + c) = v;
            }
        }
    }
}

// ---------------- per-node attention coefficients ----------------
__global__ void __launch_bounds__(256) alpha_kernel(const float* __restrict__ a_src,
                                                    const float* __restrict__ a_dst) {
    int n = blockIdx.x;
    int w = threadIdx.x >> 5, lane = threadIdx.x & 31;
    const float* hp = g_h + (size_t)n * HC + w * CH;
    float h0 = hp[lane], h1 = hp[lane + 32];
    float s = h0 * a_src[w * CH + lane] + h1 * a_src[w * CH + lane + 32];
    float d = h0 * a_dst[w * CH + lane] + h1 * a_dst[w * CH + lane + 32];
#pragma unroll
    for (int o = 16; o; o >>= 1) {
        s += __shfl_down_sync(0xffffffffu, s, o);
        d += __shfl_down_sync(0xffffffffu, d, o);
    }
    if (lane == 0) {
        g_as[n * HEADS + w] = s;
        g_ad[n * HEADS + w] = d;
    }
}

// ---------------- CSR aggregation: warp per dst node, softmax local, no atomics ----
__global__ void __launch_bounds__(256) aggregate_csr(const float* __restrict__ bias,
                                                     int elu) {
    int n    = (blockIdx.x * 256 + threadIdx.x) >> 5;
    int lane = threadIdx.x & 31;
    if (n >= N_NODES) return;
    int rs = g_rowptr[n], re = g_rowptr[n + 1];
    int h  = lane & 7;          // head for the softmax phase
    int eo = lane >> 3;         // edge offset (4 edges per iteration)
    float adv = g_ad[n * 8 + h];

    // pass 1: per-head max over incoming edges
    float m = -1e30f;
    for (int i = rs + eo; i < re; i += 4) {
        int s   = g_csrc[i];
        float l = g_as[s * 8 + h] + adv;
        l = l > 0.f ? l : 0.2f * l;
        m = fmaxf(m, l);
    }
    m = fmaxf(m, __shfl_xor_sync(0xffffffffu, m, 8));
    m = fmaxf(m, __shfl_xor_sync(0xffffffffu, m, 16));

    // pass 2: per-head denominator
    float den = 0.f;
    for (int i = rs + eo; i < re; i += 4) {
        int s   = g_csrc[i];
        float l = g_as[s * 8 + h] + adv;
        l = l > 0.f ? l : 0.2f * l;
        den += __expf(l - m);
    }
    den += __shfl_xor_sync(0xffffffffu, den, 8);
    den += __shfl_xor_sync(0xffffffffu, den, 16);
    float inv = 1.f / (den + 1e-16f);

    // pass 3: weighted gather-accumulate (32 lanes x 4 float4 = 512 floats)
    float4 acc0 = make_float4(0.f, 0.f, 0.f, 0.f);
    float4 acc1 = acc0, acc2 = acc0, acc3 = acc0;
    for (int i = rs; i < re; i++) {
        int s = g_csrc[i];
        float a8 = 0.f;
        if (lane < 8) {
            float l = g_as[s * 8 + lane] + adv;
            l  = l > 0.f ? l : 0.2f * l;
            a8 = __expf(l - m) * inv;
        }
        const float4* hs = (const float4*)(g_h + (size_t)s * HC);
        float al;
        float4 hv;
        al = __shfl_sync(0xffffffffu, a8, (lane +  0) >> 4);
        hv = hs[lane +  0];
        acc0.x += al * hv.x; acc0.y += al * hv.y; acc0.z += al * hv.z; acc0.w += al * hv.w;
        al = __shfl_sync(0xffffffffu, a8, (lane + 32) >> 4);
        hv = hs[lane + 32];
        acc1.x += al * hv.x; acc1.y += al * hv.y; acc1.z += al * hv.z; acc1.w += al * hv.w;
        al = __shfl_sync(0xffffffffu, a8, (lane + 64) >> 4);
        hv = hs[lane + 64];
        acc2.x += al * hv.x; acc2.y += al * hv.y; acc2.z += al * hv.z; acc2.w += al * hv.w;
        al = __shfl_sync(0xffffffffu, a8, (lane + 96) >> 4);
        hv = hs[lane + 96];
        acc3.x += al * hv.x; acc3.y += al * hv.y; acc3.z += al * hv.z; acc3.w += al * hv.w;
    }

    float4* yd = (float4*)(g_y + (size_t)n * HC);
    const float4* b4 = (const float4*)bias;
#pragma unroll
    for (int q = 0; q < 4; q++) {
        float4 o = (q == 0) ? acc0 : (q == 1) ? acc1 : (q == 2) ? acc2 : acc3;
        int v = lane + 32 * q;
        if (elu) {
            float4 bb = b4[v];
            o.x += bb.x; o.y += bb.y; o.z += bb.z; o.w += bb.w;
            o.x = o.x > 0.f ? o.x : expm1f(o.x);
            o.y = o.y > 0.f ? o.y : expm1f(o.y);
            o.z = o.z > 0.f ? o.z : expm1f(o.z);
            o.w = o.w > 0.f ? o.w : expm1f(o.w);
        }
        yd[v] = o;
    }
}

// ---------------- head-mean + bias3 + output projection ----------------
__global__ void __launch_bounds__(64) final_kernel(const float* __restrict__ b3,
                                                   const float* __restrict__ Wo,
                                                   const float* __restrict__ bo,
                                                   float* __restrict__ out) {
    __shared__ float s[CH];
    int n = blockIdx.x, t = threadIdx.x;   // 64 threads
    float acc = 0.f;
#pragma unroll
    for (int h = 0; h < HEADS; h++) acc += g_y[(size_t)n * HC + h * CH + t];
    s[t] = acc * 0.125f + b3[t];
    __syncthreads();
    if (t < OUTD) {
        float o = bo[t];
#pragma unroll
        for (int c = 0; c < CH; c++) o += s[c] * Wo[c * OUTD + t];
        out[n * OUTD + t] = o;
    }
}

// ---------------- launcher ----------------
extern "C" void kernel_launch(void* const* d_in, const int* in_sizes, int n_in,
                              void* d_out, int out_size) {
    const float* x     = (const float*)d_in[0];
    const void*  edges = d_in[1];
    const float* W1  = (const float*)d_in[2];
    const float* a1s = (const float*)d_in[3];
    const float* a1d = (const float*)d_in[4];
    const float* b1  = (const float*)d_in[5];
    const float* W2  = (const float*)d_in[6];
    const float* a2s = (const float*)d_in[7];
    const float* a2d = (const float*)d_in[8];
    const float* b2  = (const float*)d_in[9];
    const float* W3  = (const float*)d_in[10];
    const float* a3s = (const float*)d_in[11];
    const float* a3d = (const float*)d_in[12];
    const float* b3  = (const float*)d_in[13];
    const float* Wo  = (const float*)d_in[14];
    const float* bo  = (const float*)d_in[15];
    float* out = (float*)d_out;

    const int AGB = (N_NODES * 32 + 255) / 256;   // warp-per-node blocks
    const dim3 GG(HC / 128, (N_NODES + 127) / 128);

    // CSR build (once per launch; deterministic)
    detect_dtype<<<1, 256>>>((const unsigned*)edges);
    zero_deg<<<NBLK, 256>>>();
    convert_edges<<<(E2 + 255) / 256, 256>>>(edges);
    scan_blocks<<<NBLK, 256>>>();
    scan_bsums<<<1, 256>>>();
    finalize_rowptr<<<NBLK, 256>>>();
    scatter_edges<<<(E2 + 255) / 256, 256>>>();

    // ---- layer 1 ----
    l1_gemm<<<(N_NODES + L1_NODES - 1) / L1_NODES, 256>>>(x, W1);
    alpha_kernel<<<N_NODES, 256>>>(a1s, a1d);
    aggregate_csr<<<AGB, 256>>>(b1, 1);

    // ---- layer 2 ----  (mma_gemm reads g_y, writes g_h internally)
    mma_gemm<<<GG, 256>>>(W2);
    alpha_kernel<<<N_NODES, 256>>>(a2s, a2d);
    aggregate_csr<<<AGB, 256>>>(b2, 1);

    // ---- layer 3 ----
    mma_gemm<<<GG, 256>>>(W3);
    alpha_kernel<<<N_NODES, 256>>>(a3s, a3d);
    aggregate_csr<<<AGB, 256>>>(b3, 0);

    final_kernel<<<N_NODES, 64>>>(b3, Wo, bo, out);
}

// round 5
// speedup vs baseline: 1.6633x; 1.0927x over previous
#include <cuda_runtime.h>
#include <cuda_fp16.h>
#include <math.h>

// Problem constants (GATModel_10617159155782)
#define N_NODES 50000
#define E_IN    400000
#define E2      (E_IN + N_NODES)   // edges incl. self loops = 450000
#define HEADS   8
#define CH      64
#define HC      512                 // HEADS*CH
#define F_IN    18
#define OUTD    15
#define NBLK    ((N_NODES + 255) / 256)   // 196 scan blocks

// ---------------- scratch (device globals; allocation-free rule) ----------------
// All kernels reference these directly in device code (NEVER passed from host).
__device__ uint4 g_hh4[(size_t)N_NODES * HC / 8];   // h in fp16 (uint4 = 8 halves)
__device__ float g_y[(size_t)N_NODES * HC];         // aggregated output / next GEMM input
__device__ float g_as[N_NODES * HEADS];
__device__ float g_ad[N_NODES * HEADS];
__device__ int   g_src[E2];
__device__ int   g_dst[E2];
__device__ int   g_deg[N_NODES];
__device__ int   g_rowptr[N_NODES + 1];
__device__ int   g_cur[N_NODES];
__device__ int   g_csrc[E2];       // CSR-ordered source node per incoming edge
__device__ int   g_bsum[256];
__device__ int   g_boff[256];
__device__ int   g_is64;

// ---------------- edge index handling ----------------
__global__ void detect_dtype(const unsigned* e) {
    __shared__ int any;
    if (threadIdx.x == 0) any = 0;
    __syncthreads();
    int nz = 0;
    for (int i = threadIdx.x; i < 2048; i += 256)
        if (e[2 * i + 1] != 0u) nz = 1;          // high word of int64 would be 0
    if (nz) atomicOr(&any, 1);
    __syncthreads();
    if (threadIdx.x == 0) g_is64 = (any == 0);
}

__global__ void convert_edges(const void* ep) {
    int i = blockIdx.x * 256 + threadIdx.x;
    if (i >= E2) return;
    int s, d;
    if (i < E_IN) {
        if (g_is64) {
            const long long* p = (const long long*)ep;
            s = (int)p[i];
            d = (int)p[(size_t)E_IN + i];
        } else {
            const int* p = (const int*)ep;
            s = p[i];
            d = p[E_IN + i];
        }
    } else {
        s = i - E_IN;   // self loops
        d = i - E_IN;
    }
    g_src[i] = s;
    g_dst[i] = d;
    atomicAdd(&g_deg[d], 1);
}

__global__ void zero_deg() {
    int i = blockIdx.x * 256 + threadIdx.x;
    if (i < N_NODES) g_deg[i] = 0;
}

// ---------------- fast 3-kernel scan ----------------
__device__ __forceinline__ int block_scan_256(int v, int t, int* total) {
    __shared__ int ws[8];
    int lane = t & 31, w = t >> 5;
    int x = v;
#pragma unroll
    for (int o = 1; o < 32; o <<= 1) {
        int y = __shfl_up_sync(0xffffffffu, x, o);
        if (lane >= o) x += y;
    }
    if (lane == 31) ws[w] = x;
    __syncthreads();
    if (w == 0 && lane < 8) {
        int s = ws[lane];
#pragma unroll
        for (int o = 1; o < 8; o <<= 1) {
            int y = __shfl_up_sync(0xffu, s, o);
            if (lane >= o) s += y;
        }
        ws[lane] = s;
    }
    __syncthreads();
    int base = (w > 0) ? ws[w - 1] : 0;
    *total = ws[7];
    return base + x - v;
}

__global__ void __launch_bounds__(256) scan_blocks() {
    int b = blockIdx.x, t = threadIdx.x;
    int i = b * 256 + t;
    int v = (i < N_NODES) ? g_deg[i] : 0;
    int total;
    int ex = block_scan_256(v, t, &total);
    if (i < N_NODES) g_rowptr[i] = ex;
    if (t == 0) g_bsum[b] = total;
}

__global__ void __launch_bounds__(256) scan_bsums() {
    int t = threadIdx.x;
    int v = (t < NBLK) ? g_bsum[t] : 0;
    int total;
    int ex = block_scan_256(v, t, &total);
    g_boff[t] = ex;
}

__global__ void __launch_bounds__(256) finalize_rowptr() {
    int i = blockIdx.x * 256 + threadIdx.x;
    if (i < N_NODES) {
        int r = g_rowptr[i] + g_boff[i >> 8];
        g_rowptr[i] = r;
        g_cur[i]    = r;
    }
    if (i == 0) g_rowptr[N_NODES] = E2;
}

__global__ void scatter_edges() {
    int i = blockIdx.x * 256 + threadIdx.x;
    if (i >= E2) return;
    int p = atomicAdd(&g_cur[g_dst[i]], 1);
    g_csrc[p] = g_src[i];
}

// ---------------- layer 1 GEMM: x[N,18] @ W1[18,512] -> g_hh (fp16) ----------------
#define L1_NODES 16
__global__ void __launch_bounds__(256) l1_gemm(const float* __restrict__ x,
                                               const float* __restrict__ W) {
    __shared__ float Ws[F_IN * HC];        // 36 KB
    __shared__ float xs[L1_NODES * F_IN];
    int t = threadIdx.x;
    for (int i = t; i < F_IN * HC / 4; i += 256)
        ((float4*)Ws)[i] = ((const float4*)W)[i];
    int n0   = blockIdx.x * L1_NODES;
    int nmax = min(L1_NODES, N_NODES - n0);
    for (int i = t; i < nmax * F_IN; i += 256)
        xs[i] = x[(size_t)n0 * F_IN + i];
    __syncthreads();
    __half* hh = (__half*)g_hh4;
    // 256 threads -> 128 half2 columns per pass
    for (int r = 0; r < L1_NODES * 256; r += 256) {
        int idx = r + t;
        int nl = idx >> 8, j2 = idx & 255;       // half2 column
        if (nl < nmax) {
            int j = j2 * 2;
            float acc0 = 0.f, acc1 = 0.f;
#pragma unroll
            for (int k = 0; k < F_IN; k++) {
                float xv = xs[nl * F_IN + k];
                acc0 += xv * Ws[k * HC + j];
                acc1 += xv * Ws[k * HC + j + 1];
            }
            *(__half2*)(hh + (size_t)(n0 + nl) * HC + j) = __floats2half2_rn(acc0, acc1);
        }
    }
}

// ---------------- 3xTF32 tensor-core GEMM: g_hh = fp16(g_y @ B) ----------------
#define KT      32
#define LPAD    132
__device__ __forceinline__ unsigned f2tf32(float f) {
    unsigned r;
    asm("cvt.rna.tf32.f32 %0, %1;" : "=r"(r) : "f"(f));
    return r;
}
__device__ __forceinline__ void mma8(float* c, const unsigned* a, const unsigned* b) {
    asm volatile(
        "mma.sync.aligned.m16n8k8.row.col.f32.tf32.tf32.f32 "
        "{%0,%1,%2,%3}, {%4,%5,%6,%7}, {%8,%9}, {%0,%1,%2,%3};"
        : "+f"(c[0]), "+f"(c[1]), "+f"(c[2]), "+f"(c[3])
        : "r"(a[0]), "r"(a[1]), "r"(a[2]), "r"(a[3]), "r"(b[0]), "r"(b[1]));
}

__global__ void __launch_bounds__(256) mma_gemm(const float* __restrict__ B) {
    const int M = N_NODES, K = HC;
    __shared__ float As[KT][LPAD];   // [k][m]
    __shared__ float Bs[KT][LPAD];   // [k][n]
    int tid  = threadIdx.x;
    int lane = tid & 31, warp = tid >> 5;
    int wm = warp & 1, wn = warp >> 1;           // 2 x 4 warp grid
    int row0 = blockIdx.y * 128, col0 = blockIdx.x * 128;
    int g = lane >> 2, t4 = lane & 3;

    int arb = tid >> 3;            // A rows arb + 32q
    int ak  = (tid & 7) * 4;       // A k offset (4 contiguous)
    int bkb = tid >> 5;            // B k rows bkb + 8q
    int bc  = lane * 4;            // B cols (float4)

    float acc[4][4][4];
#pragma unroll
    for (int i = 0; i < 4; i++)
#pragma unroll
        for (int j = 0; j < 4; j++)
#pragma unroll
            for (int r = 0; r < 4; r++) acc[i][j][r] = 0.f;

    float4 ar[4], br[4];
#pragma unroll
    for (int q = 0; q < 4; q++) {
        int row = row0 + arb + 32 * q;
        ar[q] = (row < M) ? *(const float4*)(g_y + (size_t)row * K + ak)
                          : make_float4(0.f, 0.f, 0.f, 0.f);
        br[q] = *(const float4*)(B + (size_t)(bkb + 8 * q) * HC + col0 + bc);
    }

    for (int kt = 0; kt < K / KT; kt++) {
        __syncthreads();
#pragma unroll
        for (int q = 0; q < 4; q++) {
            int m = arb + 32 * q;
            As[ak + 0][m] = ar[q].x;
            As[ak + 1][m] = ar[q].y;
            As[ak + 2][m] = ar[q].z;
            As[ak + 3][m] = ar[q].w;
            *(float4*)&Bs[bkb + 8 * q][bc] = br[q];
        }
        __syncthreads();
        if (kt + 1 < K / KT) {
            int k0 = (kt + 1) * KT;
#pragma unroll
            for (int q = 0; q < 4; q++) {
                int row = row0 + arb + 32 * q;
                ar[q] = (row < M) ? *(const float4*)(g_y + (size_t)row * K + k0 + ak)
                                  : make_float4(0.f, 0.f, 0.f, 0.f);
                br[q] = *(const float4*)(B + (size_t)(k0 + bkb + 8 * q) * HC + col0 + bc);
            }
        }
#pragma unroll
        for (int k8 = 0; k8 < KT / 8; k8++) {
            int kb = k8 * 8;
            unsigned bhi[4][2], blo[4][2];
#pragma unroll
            for (int nj = 0; nj < 4; nj++) {
                int n = wn * 32 + nj * 8 + g;
                float b0 = Bs[kb + t4][n];
                float b1 = Bs[kb + t4 + 4][n];
                bhi[nj][0] = f2tf32(b0);
                bhi[nj][1] = f2tf32(b1);
                blo[nj][0] = f2tf32(b0 - __uint_as_float(bhi[nj][0]));
                blo[nj][1] = f2tf32(b1 - __uint_as_float(bhi[nj][1]));
            }
#pragma unroll
            for (int mi = 0; mi < 4; mi++) {
                int m = wm * 64 + mi * 16 + g;
                float a0 = As[kb + t4][m];
                float a1 = As[kb + t4][m + 8];
                float a2 = As[kb + t4 + 4][m];
                float a3 = As[kb + t4 + 4][m + 8];
                unsigned ahi[4], alo[4];
                ahi[0] = f2tf32(a0); alo[0] = f2tf32(a0 - __uint_as_float(ahi[0]));
                ahi[1] = f2tf32(a1); alo[1] = f2tf32(a1 - __uint_as_float(ahi[1]));
                ahi[2] = f2tf32(a2); alo[2] = f2tf32(a2 - __uint_as_float(ahi[2]));
                ahi[3] = f2tf32(a3); alo[3] = f2tf32(a3 - __uint_as_float(ahi[3]));
#pragma unroll
                for (int nj = 0; nj < 4; nj++) {
                    mma8(acc[mi][nj], ahi, bhi[nj]);
                    mma8(acc[mi][nj], ahi, blo[nj]);
                    mma8(acc[mi][nj], alo, bhi[nj]);
                }
            }
        }
    }

    // epilogue: convert to fp16 and store (half2 per 2 consecutive cols)
    __half* hh = (__half*)g_hh4;
#pragma unroll
    for (int mi = 0; mi < 4; mi++) {
#pragma unroll
        for (int nj = 0; nj < 4; nj++) {
            int r0 = row0 + wm * 64 + mi * 16 + g;
            int c  = col0 + wn * 32 + nj * 8 + 2 * t4;
            if (r0 < M)
                *(__half2*)(hh + (size_t)r0 * HC + c) =
                    __floats2half2_rn(acc[mi][nj][0], acc[mi][nj][1]);
            if (r0 + 8 < M)
                *(__half2*)(hh + (size_t)(r0 + 8) * HC + c) =
                    __floats2half2_rn(acc[mi][nj][2], acc[mi][nj][3]);
        }
    }
}

// ---------------- per-node attention coefficients (fp16 h) ----------------
__global__ void __launch_bounds__(256) alpha_kernel(const float* __restrict__ a_src,
                                                    const float* __restrict__ a_dst) {
    int n = blockIdx.x;
    int w = threadIdx.x >> 5, lane = threadIdx.x & 31;
    const __half2* hp = (const __half2*)((const __half*)g_hh4 + (size_t)n * HC + w * CH);
    float2 hv = __half22float2(hp[lane]);           // cols 2*lane, 2*lane+1
    int c = w * CH + 2 * lane;
    float s = hv.x * a_src[c] + hv.y * a_src[c + 1];
    float d = hv.x * a_dst[c] + hv.y * a_dst[c + 1];
#pragma unroll
    for (int o = 16; o; o >>= 1) {
        s += __shfl_down_sync(0xffffffffu, s, o);
        d += __shfl_down_sync(0xffffffffu, d, o);
    }
    if (lane == 0) {
        g_as[n * HEADS + w] = s;
        g_ad[n * HEADS + w] = d;
    }
}

// ---------------- CSR aggregation: warp per dst node, fp16 gather ----------------
__global__ void __launch_bounds__(256) aggregate_csr(const float* __restrict__ bias,
                                                     int elu) {
    int n    = (blockIdx.x * 256 + threadIdx.x) >> 5;
    int lane = threadIdx.x & 31;
    if (n >= N_NODES) return;
    int rs = g_rowptr[n], re = g_rowptr[n + 1];
    int h  = lane & 7;
    int eo = lane >> 3;
    float adv = g_ad[n * 8 + h];

    // pass 1: per-head max
    float m = -1e30f;
    for (int i = rs + eo; i < re; i += 4) {
        int s   = g_csrc[i];
        float l = g_as[s * 8 + h] + adv;
        l = l > 0.f ? l : 0.2f * l;
        m = fmaxf(m, l);
    }
    m = fmaxf(m, __shfl_xor_sync(0xffffffffu, m, 8));
    m = fmaxf(m, __shfl_xor_sync(0xffffffffu, m, 16));

    // pass 2: per-head denominator
    float den = 0.f;
    for (int i = rs + eo; i < re; i += 4) {
        int s   = g_csrc[i];
        float l = g_as[s * 8 + h] + adv;
        l = l > 0.f ? l : 0.2f * l;
        den += __expf(l - m);
    }
    den += __shfl_xor_sync(0xffffffffu, den, 8);
    den += __shfl_xor_sync(0xffffffffu, den, 16);
    float inv = 1.f / (den + 1e-16f);

    // pass 3: fp16 gather-accumulate. Row = 64 uint4 (8 halves each).
    // Lane handles uint4 u0=lane (cols 8*lane..) and u1=lane+32 (cols 256+8*lane..).
    float acc[16];
#pragma unroll
    for (int i = 0; i < 16; i++) acc[i] = 0.f;
    int al_src0 = lane >> 3;            // head of u0 = u0/8
    int al_src1 = (lane + 32) >> 3;     // head of u1
    for (int i = rs; i < re; i++) {
        int s = g_csrc[i];
        float a8 = 0.f;
        if (lane < 8) {
            float l = g_as[s * 8 + lane] + adv;
            l  = l > 0.f ? l : 0.2f * l;
            a8 = __expf(l - m) * inv;
        }
        float al0 = __shfl_sync(0xffffffffu, a8, al_src0);
        float al1 = __shfl_sync(0xffffffffu, a8, al_src1);
        const uint4* hs = &g_hh4[(size_t)s * (HC / 8)];
        uint4 v0 = hs[lane];
        uint4 v1 = hs[lane + 32];
        float2 f;
        f = __half22float2(*(__half2*)&v0.x); acc[0] += al0 * f.x; acc[1] += al0 * f.y;
        f = __half22float2(*(__half2*)&v0.y); acc[2] += al0 * f.x; acc[3] += al0 * f.y;
        f = __half22float2(*(__half2*)&v0.z); acc[4] += al0 * f.x; acc[5] += al0 * f.y;
        f = __half22float2(*(__half2*)&v0.w); acc[6] += al0 * f.x; acc[7] += al0 * f.y;
        f = __half22float2(*(__half2*)&v1.x); acc[8]  += al1 * f.x; acc[9]  += al1 * f.y;
        f = __half22float2(*(__half2*)&v1.y); acc[10] += al1 * f.x; acc[11] += al1 * f.y;
        f = __half22float2(*(__half2*)&v1.z); acc[12] += al1 * f.x; acc[13] += al1 * f.y;
        f = __half22float2(*(__half2*)&v1.w); acc[14] += al1 * f.x; acc[15] += al1 * f.y;
    }

    float* yd = g_y + (size_t)n * HC;
#pragma unroll
    for (int half = 0; half < 2; half++) {
        int cbase = half * 256 + 8 * lane;
#pragma unroll
        for (int q = 0; q < 2; q++) {
            float4 o;
            o.x = acc[half * 8 + q * 4 + 0];
            o.y = acc[half * 8 + q * 4 + 1];
            o.z = acc[half * 8 + q * 4 + 2];
            o.w = acc[half * 8 + q * 4 + 3];
            int c = cbase + q * 4;
            if (elu) {
                const float4 bb = *(const float4*)(bias + c);
                o.x += bb.x; o.y += bb.y; o.z += bb.z; o.w += bb.w;
                o.x = o.x > 0.f ? o.x : expm1f(o.x);
                o.y = o.y > 0.f ? o.y : expm1f(o.y);
                o.z = o.z > 0.f ? o.z : expm1f(o.z);
                o.w = o.w > 0.f ? o.w : expm1f(o.w);
            }
            *(float4*)(yd + c) = o;
        }
    }
}

// ---------------- head-mean + bias3 + output projection ----------------
__global__ void __launch_bounds__(64) final_kernel(const float* __restrict__ b3,
                                                   const float* __restrict__ Wo,
                                                   const float* __restrict__ bo,
                                                   float* __restrict__ out) {
    __shared__ float s[CH];
    int n = blockIdx.x, t = threadIdx.x;   // 64 threads
    float acc = 0.f;
#pragma unroll
    for (int h = 0; h < HEADS; h++) acc += g_y[(size_t)n * HC + h * CH + t];
    s[t] = acc * 0.125f + b3[t];
    __syncthreads();
    if (t < OUTD) {
        float o = bo[t];
#pragma unroll
        for (int c = 0; c < CH; c++) o += s[c] * Wo[c * OUTD + t];
        out[n * OUTD + t] = o;
    }
}

// ---------------- launcher ----------------
extern "C" void kernel_launch(void* const* d_in, const int* in_sizes, int n_in,
                              void* d_out, int out_size) {
    const float* x     = (const float*)d_in[0];
    const void*  edges = d_in[1];
    const float* W1  = (const float*)d_in[2];
    const float* a1s = (const float*)d_in[3];
    const float* a1d = (const float*)d_in[4];
    const float* b1  = (const float*)d_in[5];
    const float* W2  = (const float*)d_in[6];
    const float* a2s = (const float*)d_in[7];
    const float* a2d = (const float*)d_in[8];
    const float* b2  = (const float*)d_in[9];
    const float* W3  = (const float*)d_in[10];
    const float* a3s = (const float*)d_in[11];
    const float* a3d = (const float*)d_in[12];
    const float* b3  = (const float*)d_in[13];
    const float* Wo  = (const float*)d_in[14];
    const float* bo  = (const float*)d_in[15];
    float* out = (float*)d_out;

    const int AGB = (N_NODES * 32 + 255) / 256;   // warp-per-node blocks
    const dim3 GG(HC / 128, (N_NODES + 127) / 128);

    // CSR build (once per launch; deterministic)
    detect_dtype<<<1, 256>>>((const unsigned*)edges);
    zero_deg<<<NBLK, 256>>>();
    convert_edges<<<(E2 + 255) / 256, 256>>>(edges);
    scan_blocks<<<NBLK, 256>>>();
    scan_bsums<<<1, 256>>>();
    finalize_rowptr<<<NBLK, 256>>>();
    scatter_edges<<<(E2 + 255) / 256, 256>>>();

    // ---- layer 1 ----
    l1_gemm<<<(N_NODES + L1_NODES - 1) / L1_NODES, 256>>>(x, W1);
    alpha_kernel<<<N_NODES, 256>>>(a1s, a1d);
    aggregate_csr<<<AGB, 256>>>(b1, 1);

    // ---- layer 2 ----
    mma_gemm<<<GG, 256>>>(W2);
    alpha_kernel<<<N_NODES, 256>>>(a2s, a2d);
    aggregate_csr<<<AGB, 256>>>(b2, 1);

    // ---- layer 3 ----
    mma_gemm<<<GG, 256>>>(W3);
    alpha_kernel<<<N_NODES, 256>>>(a3s, a3d);
    aggregate_csr<<<AGB, 256>>>(b3, 0);

    final_kernel<<<N_NODES, 64>>>(b3, Wo, bo, out);
}

// round 7
// speedup vs baseline: 2.5023x; 1.5044x over previous
#include <cuda_runtime.h>
#include <cuda_fp16.h>
#include <math.h>

// Problem constants (GATModel_10617159155782)
#define N_NODES 50000
#define E_IN    400000
#define E2      (E_IN + N_NODES)   // edges incl. self loops = 450000
#define HEADS   8
#define CH      64
#define HC      512                 // HEADS*CH
#define F_IN    18
#define OUTD    15
#define NBLK    ((N_NODES + 255) / 256)   // 196 scan blocks

// ---------------- scratch (device globals; allocation-free rule) ----------------
__device__ uint4 g_hh4[(size_t)N_NODES * HC / 8];   // h  in fp16 (uint4 = 8 halves)
__device__ uint4 g_yh4[(size_t)N_NODES * HC / 8];   // y  in fp16 (GEMM A input)
__device__ float g_y[(size_t)N_NODES * HC];         // layer-3 y in fp32 (final proj input)
__device__ float g_as[N_NODES * HEADS];
__device__ float g_ad[N_NODES * HEADS];
__device__ int   g_src[E2];
__device__ int   g_dst[E2];
__device__ int   g_deg[N_NODES];
__device__ int   g_rowptr[N_NODES + 1];
__device__ int   g_cur[N_NODES];
__device__ int   g_csrc[E2];
__device__ int   g_bsum[256];
__device__ int   g_boff[256];
__device__ int   g_is64;

// ---------------- edge index handling ----------------
__global__ void detect_dtype(const unsigned* e) {
    __shared__ int any;
    if (threadIdx.x == 0) any = 0;
    __syncthreads();
    int nz = 0;
    for (int i = threadIdx.x; i < 2048; i += 256)
        if (e[2 * i + 1] != 0u) nz = 1;
    if (nz) atomicOr(&any, 1);
    __syncthreads();
    if (threadIdx.x == 0) g_is64 = (any == 0);
}

__global__ void convert_edges(const void* ep) {
    int i = blockIdx.x * 256 + threadIdx.x;
    if (i >= E2) return;
    int s, d;
    if (i < E_IN) {
        if (g_is64) {
            const long long* p = (const long long*)ep;
            s = (int)p[i];
            d = (int)p[(size_t)E_IN + i];
        } else {
            const int* p = (const int*)ep;
            s = p[i];
            d = p[E_IN + i];
        }
    } else {
        s = i - E_IN;
        d = i - E_IN;
    }
    g_src[i] = s;
    g_dst[i] = d;
    atomicAdd(&g_deg[d], 1);
}

__global__ void zero_deg() {
    int i = blockIdx.x * 256 + threadIdx.x;
    if (i < N_NODES) g_deg[i] = 0;
}

// ---------------- fast 3-kernel scan ----------------
__device__ __forceinline__ int block_scan_256(int v, int t, int* total) {
    __shared__ int ws[8];
    int lane = t & 31, w = t >> 5;
    int x = v;
#pragma unroll
    for (int o = 1; o < 32; o <<= 1) {
        int y = __shfl_up_sync(0xffffffffu, x, o);
        if (lane >= o) x += y;
    }
    if (lane == 31) ws[w] = x;
    __syncthreads();
    if (w == 0 && lane < 8) {
        int s = ws[lane];
#pragma unroll
        for (int o = 1; o < 8; o <<= 1) {
            int y = __shfl_up_sync(0xffu, s, o);
            if (lane >= o) s += y;
        }
        ws[lane] = s;
    }
    __syncthreads();
    int base = (w > 0) ? ws[w - 1] : 0;
    *total = ws[7];
    return base + x - v;
}

__global__ void __launch_bounds__(256) scan_blocks() {
    int b = blockIdx.x, t = threadIdx.x;
    int i = b * 256 + t;
    int v = (i < N_NODES) ? g_deg[i] : 0;
    int total;
    int ex = block_scan_256(v, t, &total);
    if (i < N_NODES) g_rowptr[i] = ex;
    if (t == 0) g_bsum[b] = total;
}

__global__ void __launch_bounds__(256) scan_bsums() {
    int t = threadIdx.x;
    int v = (t < NBLK) ? g_bsum[t] : 0;
    int total;
    int ex = block_scan_256(v, t, &total);
    g_boff[t] = ex;
}

__global__ void __launch_bounds__(256) finalize_rowptr() {
    int i = blockIdx.x * 256 + threadIdx.x;
    if (i < N_NODES) {
        int r = g_rowptr[i] + g_boff[i >> 8];
        g_rowptr[i] = r;
        g_cur[i]    = r;
    }
    if (i == 0) g_rowptr[N_NODES] = E2;
}

__global__ void scatter_edges() {
    int i = blockIdx.x * 256 + threadIdx.x;
    if (i >= E2) return;
    int p = atomicAdd(&g_cur[g_dst[i]], 1);
    g_csrc[p] = g_src[i];
}

// ---------------- layer 1 GEMM: x[N,18] @ W1[18,512] -> g_hh (fp16) ----------------
#define L1_NODES 16
__global__ void __launch_bounds__(256) l1_gemm(const float* __restrict__ x,
                                               const float* __restrict__ W) {
    __shared__ float Ws[F_IN * HC];
    __shared__ float xs[L1_NODES * F_IN];
    int t = threadIdx.x;
    for (int i = t; i < F_IN * HC / 4; i += 256)
        ((float4*)Ws)[i] = ((const float4*)W)[i];
    int n0   = blockIdx.x * L1_NODES;
    int nmax = min(L1_NODES, N_NODES - n0);
    for (int i = t; i < nmax * F_IN; i += 256)
        xs[i] = x[(size_t)n0 * F_IN + i];
    __syncthreads();
    __half* hh = (__half*)g_hh4;
    for (int r = 0; r < L1_NODES * 256; r += 256) {
        int idx = r + t;
        int nl = idx >> 8, j2 = idx & 255;
        if (nl < nmax) {
            int j = j2 * 2;
            float acc0 = 0.f, acc1 = 0.f;
#pragma unroll
            for (int k = 0; k < F_IN; k++) {
                float xv = xs[nl * F_IN + k];
                acc0 += xv * Ws[k * HC + j];
                acc1 += xv * Ws[k * HC + j + 1];
            }
            *(__half2*)(hh + (size_t)(n0 + nl) * HC + j) = __floats2half2_rn(acc0, acc1);
        }
    }
}

// ---------------- split-fp16 tensor GEMM: g_hh = fp16(g_yh @ B) ----------------
// A exact fp16; B fp32 split into hi+lo fp16 at smem-load time. 2 MMA passes.
#define KT   32
#define APAD 40    // 80B row stride: keeps uint4 stores 16B-aligned, conflict-free frags
#define BPAD 36

__device__ __forceinline__ void mma16(float* c, const unsigned* a, const unsigned* b) {
    asm volatile(
        "mma.sync.aligned.m16n8k16.row.col.f32.f16.f16.f32 "
        "{%0,%1,%2,%3}, {%4,%5,%6,%7}, {%8,%9}, {%0,%1,%2,%3};"
        : "+f"(c[0]), "+f"(c[1]), "+f"(c[2]), "+f"(c[3])
        : "r"(a[0]), "r"(a[1]), "r"(a[2]), "r"(a[3]), "r"(b[0]), "r"(b[1]));
}

__global__ void __launch_bounds__(256) hgemm(const float* __restrict__ B) {
    const int M = N_NODES, K = HC;
    __shared__ __half As[128][APAD];   // [m][k]
    __shared__ __half Bh[128][BPAD];   // [n][k] hi
    __shared__ __half Bl[128][BPAD];   // [n][k] lo
    int tid  = threadIdx.x;
    int lane = tid & 31, warp = tid >> 5;
    int wm = warp & 1, wn = warp >> 1;            // 2x4 warp grid, 64x32 warp tiles
    int row0 = blockIdx.y * 128, col0 = blockIdx.x * 128;
    int g = lane >> 2, t2 = (lane & 3) * 2;

    // A loader: r = (tid>>2) + 64*it, u4 col = tid&3  (32 halves/row = 4 uint4)
    int ar = tid >> 2, au = tid & 3;
    // B loader: k = tid>>3 (0..31), f4 = (tid&7) + 8*it
    int bk = tid >> 3, bf = tid & 7;

    const __half* Agl = (const __half*)g_yh4;

    float acc[4][4][4];
#pragma unroll
    for (int i = 0; i < 4; i++)
#pragma unroll
        for (int j = 0; j < 4; j++)
#pragma unroll
            for (int r = 0; r < 4; r++) acc[i][j][r] = 0.f;

    uint4  apre[2];
    float4 bpre[4];
    // prefetch chunk 0
#pragma unroll
    for (int it = 0; it < 2; it++) {
        int row = row0 + ar + 64 * it;
        apre[it] = (row < M) ? *(const uint4*)(Agl + (size_t)row * K + au * 8)
                             : make_uint4(0u, 0u, 0u, 0u);
    }
#pragma unroll
    for (int it = 0; it < 4; it++)
        bpre[it] = *(const float4*)(B + (size_t)bk * HC + col0 + (bf + 8 * it) * 4);

    for (int kt = 0; kt < K / KT; kt++) {
        // store prefetched chunk to smem
#pragma unroll
        for (int it = 0; it < 2; it++)
            *(uint4*)&As[ar + 64 * it][au * 8] = apre[it];
#pragma unroll
        for (int it = 0; it < 4; it++) {
            int f4 = bf + 8 * it;
            const float* v = &bpre[it].x;
#pragma unroll
            for (int j = 0; j < 4; j++) {
                int n = f4 * 4 + j;
                __half hi = __float2half_rn(v[j]);
                __half lo = __float2half_rn(v[j] - __half2float(hi));
                Bh[n][bk] = hi;
                Bl[n][bk] = lo;
            }
        }
        __syncthreads();
        // prefetch next chunk
        if (kt + 1 < K / KT) {
            int k0 = (kt + 1) * KT;
#pragma unroll
            for (int it = 0; it < 2; it++) {
                int row = row0 + ar + 64 * it;
                apre[it] = (row < M) ? *(const uint4*)(Agl + (size_t)row * K + k0 + au * 8)
                                     : make_uint4(0u, 0u, 0u, 0u);
            }
#pragma unroll
            for (int it = 0; it < 4; it++)
                bpre[it] = *(const float4*)(B + (size_t)(k0 + bk) * HC + col0 + (bf + 8 * it) * 4);
        }
        // 2 k16 steps per chunk
#pragma unroll
        for (int kk = 0; kk < KT; kk += 16) {
            unsigned bhf[4][2], blf[4][2];
#pragma unroll
            for (int nj = 0; nj < 4; nj++) {
                int n = wn * 32 + nj * 8 + g;
                bhf[nj][0] = *(const unsigned*)&Bh[n][kk + t2];
                bhf[nj][1] = *(const unsigned*)&Bh[n][kk + t2 + 8];
                blf[nj][0] = *(const unsigned*)&Bl[n][kk + t2];
                blf[nj][1] = *(const unsigned*)&Bl[n][kk + t2 + 8];
            }
#pragma unroll
            for (int mi = 0; mi < 4; mi++) {
                int m = wm * 64 + mi * 16 + g;
                unsigned af[4];
                af[0] = *(const unsigned*)&As[m][kk + t2];
                af[1] = *(const unsigned*)&As[m + 8][kk + t2];
                af[2] = *(const unsigned*)&As[m][kk + t2 + 8];
                af[3] = *(const unsigned*)&As[m + 8][kk + t2 + 8];
#pragma unroll
                for (int nj = 0; nj < 4; nj++) {
                    mma16(acc[mi][nj], af, bhf[nj]);
                    mma16(acc[mi][nj], af, blf[nj]);
                }
            }
        }
        __syncthreads();
    }

    // epilogue: fp16 store
    __half* hh = (__half*)g_hh4;
#pragma unroll
    for (int mi = 0; mi < 4; mi++) {
#pragma unroll
        for (int nj = 0; nj < 4; nj++) {
            int r0 = row0 + wm * 64 + mi * 16 + g;
            int c  = col0 + wn * 32 + nj * 8 + t2;
            if (r0 < M)
                *(__half2*)(hh + (size_t)r0 * HC + c) =
                    __floats2half2_rn(acc[mi][nj][0], acc[mi][nj][1]);
            if (r0 + 8 < M)
                *(__half2*)(hh + (size_t)(r0 + 8) * HC + c) =
                    __floats2half2_rn(acc[mi][nj][2], acc[mi][nj][3]);
        }
    }
}

// ---------------- per-node attention coefficients (fp16 h) ----------------
__global__ void __launch_bounds__(256) alpha_kernel(const float* __restrict__ a_src,
                                                    const float* __restrict__ a_dst) {
    int n = blockIdx.x;
    int w = threadIdx.x >> 5, lane = threadIdx.x & 31;
    const __half2* hp = (const __half2*)((const __half*)g_hh4 + (size_t)n * HC + w * CH);
    float2 hv = __half22float2(hp[lane]);
    int c = w * CH + 2 * lane;
    float s = hv.x * a_src[c] + hv.y * a_src[c + 1];
    float d = hv.x * a_dst[c] + hv.y * a_dst[c + 1];
#pragma unroll
    for (int o = 16; o; o >>= 1) {
        s += __shfl_down_sync(0xffffffffu, s, o);
        d += __shfl_down_sync(0xffffffffu, d, o);
    }
    if (lane == 0) {
        g_as[n * HEADS + w] = s;
        g_ad[n * HEADS + w] = d;
    }
}

// ---------------- CSR aggregation: warp per dst node, fp16 gather ----------------
// elu=1: bias+ELU, store fp16 to g_yh4 (layers 1,2). elu=0: store fp32 to g_y (layer 3).
__global__ void __launch_bounds__(256) aggregate_csr(const float* __restrict__ bias,
                                                     int elu) {
    int n    = (blockIdx.x * 256 + threadIdx.x) >> 5;
    int lane = threadIdx.x & 31;
    if (n >= N_NODES) return;
    int rs = g_rowptr[n], re = g_rowptr[n + 1];
    int h  = lane & 7;
    int eo = lane >> 3;
    float adv = g_ad[n * 8 + h];

    float m = -1e30f;
    for (int i = rs + eo; i < re; i += 4) {
        int s   = g_csrc[i];
        float l = g_as[s * 8 + h] + adv;
        l = l > 0.f ? l : 0.2f * l;
        m = fmaxf(m, l);
    }
    m = fmaxf(m, __shfl_xor_sync(0xffffffffu, m, 8));
    m = fmaxf(m, __shfl_xor_sync(0xffffffffu, m, 16));

    float den = 0.f;
    for (int i = rs + eo; i < re; i += 4) {
        int s   = g_csrc[i];
        float l = g_as[s * 8 + h] + adv;
        l = l > 0.f ? l : 0.2f * l;
        den += __expf(l - m);
    }
    den += __shfl_xor_sync(0xffffffffu, den, 8);
    den += __shfl_xor_sync(0xffffffffu, den, 16);
    float inv = 1.f / (den + 1e-16f);

    float acc[16];
#pragma unroll
    for (int i = 0; i < 16; i++) acc[i] = 0.f;
    int al_src0 = lane >> 3;
    int al_src1 = (lane + 32) >> 3;
    for (int i = rs; i < re; i++) {
        int s = g_csrc[i];
        float a8 = 0.f;
        if (lane < 8) {
            float l = g_as[s * 8 + lane] + adv;
            l  = l > 0.f ? l : 0.2f * l;
            a8 = __expf(l - m) * inv;
        }
        float al0 = __shfl_sync(0xffffffffu, a8, al_src0);
        float al1 = __shfl_sync(0xffffffffu, a8, al_src1);
        const uint4* hs = &g_hh4[(size_t)s * (HC / 8)];
        uint4 v0 = hs[lane];
        uint4 v1 = hs[lane + 32];
        float2 f;
        f = __half22float2(*(__half2*)&v0.x); acc[0] += al0 * f.x; acc[1] += al0 * f.y;
        f = __half22float2(*(__half2*)&v0.y); acc[2] += al0 * f.x; acc[3] += al0 * f.y;
        f = __half22float2(*(__half2*)&v0.z); acc[4] += al0 * f.x; acc[5] += al0 * f.y;
        f = __half22float2(*(__half2*)&v0.w); acc[6] += al0 * f.x; acc[7] += al0 * f.y;
        f = __half22float2(*(__half2*)&v1.x); acc[8]  += al1 * f.x; acc[9]  += al1 * f.y;
        f = __half22float2(*(__half2*)&v1.y); acc[10] += al1 * f.x; acc[11] += al1 * f.y;
        f = __half22float2(*(__half2*)&v1.z); acc[12] += al1 * f.x; acc[13] += al1 * f.y;
        f = __half22float2(*(__half2*)&v1.w); acc[14] += al1 * f.x; acc[15] += al1 * f.y;
    }

    if (elu) {
        __half* yh = (__half*)g_yh4 + (size_t)n * HC;
#pragma unroll
        for (int half = 0; half < 2; half++) {
            int cbase = half * 256 + 8 * lane;
            __half2 o4[4];
#pragma unroll
            for (int q = 0; q < 4; q++) {
                int c  = cbase + q * 2;
                float v0 = acc[half * 8 + q * 2 + 0] + bias[c];
                float v1 = acc[half * 8 + q * 2 + 1] + bias[c + 1];
                v0 = v0 > 0.f ? v0 : expm1f(v0);
                v1 = v1 > 0.f ? v1 : expm1f(v1);
                o4[q] = __floats2half2_rn(v0, v1);
            }
            *(uint4*)(yh + cbase) = *(uint4*)o4;
        }
    } else {
        float* yd = g_y + (size_t)n * HC;
#pragma unroll
        for (int half = 0; half < 2; half++) {
            int cbase = half * 256 + 8 * lane;
#pragma unroll
            for (int q = 0; q < 2; q++) {
                float4 o;
                o.x = acc[half * 8 + q * 4 + 0];
                o.y = acc[half * 8 + q * 4 + 1];
                o.z = acc[half * 8 + q * 4 + 2];
                o.w = acc[half * 8 + q * 4 + 3];
                *(float4*)(yd + cbase + q * 4) = o;
            }
        }
    }
}

// ---------------- head-mean + bias3 + output projection ----------------
__global__ void __launch_bounds__(64) final_kernel(const float* __restrict__ b3,
                                                   const float* __restrict__ Wo,
                                                   const float* __restrict__ bo,
                                                   float* __restrict__ out) {
    __shared__ float s[CH];
    int n = blockIdx.x, t = threadIdx.x;
    float acc = 0.f;
#pragma unroll
    for (int h = 0; h < HEADS; h++) acc += g_y[(size_t)n * HC + h * CH + t];
    s[t] = acc * 0.125f + b3[t];
    __syncthreads();
    if (t < OUTD) {
        float o = bo[t];
#pragma unroll
        for (int c = 0; c < CH; c++) o += s[c] * Wo[c * OUTD + t];
        out[n * OUTD + t] = o;
    }
}

// ---------------- launcher ----------------
extern "C" void kernel_launch(void* const* d_in, const int* in_sizes, int n_in,
                              void* d_out, int out_size) {
    const float* x     = (const float*)d_in[0];
    const void*  edges = d_in[1];
    const float* W1  = (const float*)d_in[2];
    const float* a1s = (const float*)d_in[3];
    const float* a1d = (const float*)d_in[4];
    const float* b1  = (const float*)d_in[5];
    const float* W2  = (const float*)d_in[6];
    const float* a2s = (const float*)d_in[7];
    const float* a2d = (const float*)d_in[8];
    const float* b2  = (const float*)d_in[9];
    const float* W3  = (const float*)d_in[10];
    const float* a3s = (const float*)d_in[11];
    const float* a3d = (const float*)d_in[12];
    const float* b3  = (const float*)d_in[13];
    const float* Wo  = (const float*)d_in[14];
    const float* bo  = (const float*)d_in[15];
    float* out = (float*)d_out;

    const int AGB = (N_NODES * 32 + 255) / 256;
    const dim3 GG(HC / 128, (N_NODES + 127) / 128);

    detect_dtype<<<1, 256>>>((const unsigned*)edges);
    zero_deg<<<NBLK, 256>>>();
    convert_edges<<<(E2 + 255) / 256, 256>>>(edges);
    scan_blocks<<<NBLK, 256>>>();
    scan_bsums<<<1, 256>>>();
    finalize_rowptr<<<NBLK, 256>>>();
    scatter_edges<<<(E2 + 255) / 256, 256>>>();

    // ---- layer 1 ----
    l1_gemm<<<(N_NODES + L1_NODES - 1) / L1_NODES, 256>>>(x, W1);
    alpha_kernel<<<N_NODES, 256>>>(a1s, a1d);
    aggregate_csr<<<AGB, 256>>>(b1, 1);

    // ---- layer 2 ----
    hgemm<<<GG, 256>>>(W2);
    alpha_kernel<<<N_NODES, 256>>>(a2s, a2d);
    aggregate_csr<<<AGB, 256>>>(b2, 1);

    // ---- layer 3 ----
    hgemm<<<GG, 256>>>(W3);
    alpha_kernel<<<N_NODES, 256>>>(a3s, a3d);
    aggregate_csr<<<AGB, 256>>>(b3, 0);

    final_kernel<<<N_NODES, 64>>>(b3, Wo, bo, out);
}

// round 8
// speedup vs baseline: 2.5037x; 1.0006x over previous
#include <cuda_runtime.h>
#include <cuda_fp16.h>
#include <math.h>

// Problem constants (GATModel_10617159155782)
#define N_NODES 50000
#define E_IN    400000
#define E2      (E_IN + N_NODES)   // edges incl. self loops = 450000
#define HEADS   8
#define CH      64
#define HC      512                 // HEADS*CH
#define F_IN    18
#define OUTD    15
#define NBLK    ((N_NODES + 255) / 256)   // 196 scan blocks

// ---------------- scratch (device globals; allocation-free rule) ----------------
__device__ uint4 g_hh4[(size_t)N_NODES * HC / 8];   // h  in fp16 (uint4 = 8 halves)
__device__ uint4 g_yh4[(size_t)N_NODES * HC / 8];   // y  in fp16 (GEMM A input)
__device__ float g_y[(size_t)N_NODES * HC];         // layer-3 y in fp32 (final proj input)
__device__ float g_as[N_NODES * HEADS];
__device__ float g_ad[N_NODES * HEADS];
__device__ int   g_src[E2];
__device__ int   g_dst[E2];
__device__ int   g_deg[N_NODES];
__device__ int   g_rowptr[N_NODES + 1];
__device__ int   g_cur[N_NODES];
__device__ int   g_csrc[E2];
__device__ int   g_bsum[256];
__device__ int   g_boff[256];
__device__ int   g_is64;

// ---------------- edge index handling ----------------
__global__ void detect_dtype(const unsigned* e) {
    __shared__ int any;
    if (threadIdx.x == 0) any = 0;
    __syncthreads();
    int nz = 0;
    for (int i = threadIdx.x; i < 2048; i += 256)
        if (e[2 * i + 1] != 0u) nz = 1;
    if (nz) atomicOr(&any, 1);
    __syncthreads();
    if (threadIdx.x == 0) g_is64 = (any == 0);
}

__global__ void convert_edges(const void* ep) {
    int i = blockIdx.x * 256 + threadIdx.x;
    if (i >= E2) return;
    int s, d;
    if (i < E_IN) {
        if (g_is64) {
            const long long* p = (const long long*)ep;
            s = (int)p[i];
            d = (int)p[(size_t)E_IN + i];
        } else {
            const int* p = (const int*)ep;
            s = p[i];
            d = p[E_IN + i];
        }
    } else {
        s = i - E_IN;
        d = i - E_IN;
    }
    g_src[i] = s;
    g_dst[i] = d;
    atomicAdd(&g_deg[d], 1);
}

__global__ void zero_deg() {
    int i = blockIdx.x * 256 + threadIdx.x;
    if (i < N_NODES) g_deg[i] = 0;
}

// ---------------- fast 3-kernel scan ----------------
__device__ __forceinline__ int block_scan_256(int v, int t, int* total) {
    __shared__ int ws[8];
    int lane = t & 31, w = t >> 5;
    int x = v;
#pragma unroll
    for (int o = 1; o < 32; o <<= 1) {
        int y = __shfl_up_sync(0xffffffffu, x, o);
        if (lane >= o) x += y;
    }
    if (lane == 31) ws[w] = x;
    __syncthreads();
    if (w == 0 && lane < 8) {
        int s = ws[lane];
#pragma unroll
        for (int o = 1; o < 8; o <<= 1) {
            int y = __shfl_up_sync(0xffu, s, o);
            if (lane >= o) s += y;
        }
        ws[lane] = s;
    }
    __syncthreads();
    int base = (w > 0) ? ws[w - 1] : 0;
    *total = ws[7];
    return base + x - v;
}

__global__ void __launch_bounds__(256) scan_blocks() {
    int b = blockIdx.x, t = threadIdx.x;
    int i = b * 256 + t;
    int v = (i < N_NODES) ? g_deg[i] : 0;
    int total;
    int ex = block_scan_256(v, t, &total);
    if (i < N_NODES) g_rowptr[i] = ex;
    if (t == 0) g_bsum[b] = total;
}

__global__ void __launch_bounds__(256) scan_bsums() {
    int t = threadIdx.x;
    int v = (t < NBLK) ? g_bsum[t] : 0;
    int total;
    int ex = block_scan_256(v, t, &total);
    g_boff[t] = ex;
}

__global__ void __launch_bounds__(256) finalize_rowptr() {
    int i = blockIdx.x * 256 + threadIdx.x;
    if (i < N_NODES) {
        int r = g_rowptr[i] + g_boff[i >> 8];
        g_rowptr[i] = r;
        g_cur[i]    = r;
    }
    if (i == 0) g_rowptr[N_NODES] = E2;
}

__global__ void scatter_edges() {
    int i = blockIdx.x * 256 + threadIdx.x;
    if (i >= E2) return;
    int p = atomicAdd(&g_cur[g_dst[i]], 1);
    g_csrc[p] = g_src[i];
}

// ---------------- layer 1 GEMM: x[N,18] @ W1[18,512] -> g_hh (fp16) ----------------
#define L1_NODES 16
__global__ void __launch_bounds__(256) l1_gemm(const float* __restrict__ x,
                                               const float* __restrict__ W) {
    __shared__ float Ws[F_IN * HC];
    __shared__ float xs[L1_NODES * F_IN];
    int t = threadIdx.x;
    for (int i = t; i < F_IN * HC / 4; i += 256)
        ((float4*)Ws)[i] = ((const float4*)W)[i];
    int n0   = blockIdx.x * L1_NODES;
    int nmax = min(L1_NODES, N_NODES - n0);
    for (int i = t; i < nmax * F_IN; i += 256)
        xs[i] = x[(size_t)n0 * F_IN + i];
    __syncthreads();
    __half* hh = (__half*)g_hh4;
    for (int r = 0; r < L1_NODES * 256; r += 256) {
        int idx = r + t;
        int nl = idx >> 8, j2 = idx & 255;
        if (nl < nmax) {
            int j = j2 * 2;
            float acc0 = 0.f, acc1 = 0.f;
#pragma unroll
            for (int k = 0; k < F_IN; k++) {
                float xv = xs[nl * F_IN + k];
                acc0 += xv * Ws[k * HC + j];
                acc1 += xv * Ws[k * HC + j + 1];
            }
            *(__half2*)(hh + (size_t)(n0 + nl) * HC + j) = __floats2half2_rn(acc0, acc1);
        }
    }
}

// ---------------- split-fp16 tensor GEMM: g_hh = fp16(g_yh @ B) ----------------
// A exact fp16; B fp32 split into hi+lo fp16 at smem-load time. 2 MMA passes.
#define KT   32
#define APAD 40    // 80B row stride: keeps uint4 stores 16B-aligned, conflict-free frags
#define BPAD 36

__device__ __forceinline__ void mma16(float* c, const unsigned* a, const unsigned* b) {
    asm volatile(
        "mma.sync.aligned.m16n8k16.row.col.f32.f16.f16.f32 "
        "{%0,%1,%2,%3}, {%4,%5,%6,%7}, {%8,%9}, {%0,%1,%2,%3};"
        : "+f"(c[0]), "+f"(c[1]), "+f"(c[2]), "+f"(c[3])
        : "r"(a[0]), "r"(a[1]), "r"(a[2]), "r"(a[3]), "r"(b[0]), "r"(b[1]));
}

__global__ void __launch_bounds__(256) hgemm(const float* __restrict__ B) {
    const int M = N_NODES, K = HC;
    __shared__ __half As[128][APAD];   // [m][k]
    __shared__ __half Bh[128][BPAD];   // [n][k] hi
    __shared__ __half Bl[128][BPAD];   // [n][k] lo
    int tid  = threadIdx.x;
    int lane = tid & 31, warp = tid >> 5;
    int wm = warp & 1, wn = warp >> 1;            // 2x4 warp grid, 64x32 warp tiles
    int row0 = blockIdx.y * 128, col0 = blockIdx.x * 128;
    int g = lane >> 2, t2 = (lane & 3) * 2;

    // A loader: r = (tid>>2) + 64*it, u4 col = tid&3  (32 halves/row = 4 uint4)
    int ar = tid >> 2, au = tid & 3;
    // B loader: k = tid>>3 (0..31), f4 = (tid&7) + 8*it
    int bk = tid >> 3, bf = tid & 7;

    const __half* Agl = (const __half*)g_yh4;

    float acc[4][4][4];
#pragma unroll
    for (int i = 0; i < 4; i++)
#pragma unroll
        for (int j = 0; j < 4; j++)
#pragma unroll
            for (int r = 0; r < 4; r++) acc[i][j][r] = 0.f;

    uint4  apre[2];
    float4 bpre[4];
    // prefetch chunk 0
#pragma unroll
    for (int it = 0; it < 2; it++) {
        int row = row0 + ar + 64 * it;
        apre[it] = (row < M) ? *(const uint4*)(Agl + (size_t)row * K + au * 8)
                             : make_uint4(0u, 0u, 0u, 0u);
    }
#pragma unroll
    for (int it = 0; it < 4; it++)
        bpre[it] = *(const float4*)(B + (size_t)bk * HC + col0 + (bf + 8 * it) * 4);

    for (int kt = 0; kt < K / KT; kt++) {
        // store prefetched chunk to smem
#pragma unroll
        for (int it = 0; it < 2; it++)
            *(uint4*)&As[ar + 64 * it][au * 8] = apre[it];
#pragma unroll
        for (int it = 0; it < 4; it++) {
            int f4 = bf + 8 * it;
            const float* v = &bpre[it].x;
#pragma unroll
            for (int j = 0; j < 4; j++) {
                int n = f4 * 4 + j;
                __half hi = __float2half_rn(v[j]);
                __half lo = __float2half_rn(v[j] - __half2float(hi));
                Bh[n][bk] = hi;
                Bl[n][bk] = lo;
            }
        }
        __syncthreads();
        // prefetch next chunk
        if (kt + 1 < K / KT) {
            int k0 = (kt + 1) * KT;
#pragma unroll
            for (int it = 0; it < 2; it++) {
                int row = row0 + ar + 64 * it;
                apre[it] = (row < M) ? *(const uint4*)(Agl + (size_t)row * K + k0 + au * 8)
                                     : make_uint4(0u, 0u, 0u, 0u);
            }
#pragma unroll
            for (int it = 0; it < 4; it++)
                bpre[it] = *(const float4*)(B + (size_t)(k0 + bk) * HC + col0 + (bf + 8 * it) * 4);
        }
        // 2 k16 steps per chunk
#pragma unroll
        for (int kk = 0; kk < KT; kk += 16) {
            unsigned bhf[4][2], blf[4][2];
#pragma unroll
            for (int nj = 0; nj < 4; nj++) {
                int n = wn * 32 + nj * 8 + g;
                bhf[nj][0] = *(const unsigned*)&Bh[n][kk + t2];
                bhf[nj][1] = *(const unsigned*)&Bh[n][kk + t2 + 8];
                blf[nj][0] = *(const unsigned*)&Bl[n][kk + t2];
                blf[nj][1] = *(const unsigned*)&Bl[n][kk + t2 + 8];
            }
#pragma unroll
            for (int mi = 0; mi < 4; mi++) {
                int m = wm * 64 + mi * 16 + g;
                unsigned af[4];
                af[0] = *(const unsigned*)&As[m][kk + t2];
                af[1] = *(const unsigned*)&As[m + 8][kk + t2];
                af[2] = *(const unsigned*)&As[m][kk + t2 + 8];
                af[3] = *(const unsigned*)&As[m + 8][kk + t2 + 8];
#pragma unroll
                for (int nj = 0; nj < 4; nj++) {
                    mma16(acc[mi][nj], af, bhf[nj]);
                    mma16(acc[mi][nj], af, blf[nj]);
                }
            }
        }
        __syncthreads();
    }

    // epilogue: fp16 store
    __half* hh = (__half*)g_hh4;
#pragma unroll
    for (int mi = 0; mi < 4; mi++) {
#pragma unroll
        for (int nj = 0; nj < 4; nj++) {
            int r0 = row0 + wm * 64 + mi * 16 + g;
            int c  = col0 + wn * 32 + nj * 8 + t2;
            if (r0 < M)
                *(__half2*)(hh + (size_t)r0 * HC + c) =
                    __floats2half2_rn(acc[mi][nj][0], acc[mi][nj][1]);
            if (r0 + 8 < M)
                *(__half2*)(hh + (size_t)(r0 + 8) * HC + c) =
                    __floats2half2_rn(acc[mi][nj][2], acc[mi][nj][3]);
        }
    }
}

// ---------------- per-node attention coefficients (fp16 h) ----------------
__global__ void __launch_bounds__(256) alpha_kernel(const float* __restrict__ a_src,
                                                    const float* __restrict__ a_dst) {
    int n = blockIdx.x;
    int w = threadIdx.x >> 5, lane = threadIdx.x & 31;
    const __half2* hp = (const __half2*)((const __half*)g_hh4 + (size_t)n * HC + w * CH);
    float2 hv = __half22float2(hp[lane]);
    int c = w * CH + 2 * lane;
    float s = hv.x * a_src[c] + hv.y * a_src[c + 1];
    float d = hv.x * a_dst[c] + hv.y * a_dst[c + 1];
#pragma unroll
    for (int o = 16; o; o >>= 1) {
        s += __shfl_down_sync(0xffffffffu, s, o);
        d += __shfl_down_sync(0xffffffffu, d, o);
    }
    if (lane == 0) {
        g_as[n * HEADS + w] = s;
        g_ad[n * HEADS + w] = d;
    }
}

// ---------------- CSR aggregation: warp per dst node, fp16 gather ----------------
// elu=1: bias+ELU, store fp16 to g_yh4 (layers 1,2). elu=0: store fp32 to g_y (layer 3).
__global__ void __launch_bounds__(256) aggregate_csr(const float* __restrict__ bias,
                                                     int elu) {
    int n    = (blockIdx.x * 256 + threadIdx.x) >> 5;
    int lane = threadIdx.x & 31;
    if (n >= N_NODES) return;
    int rs = g_rowptr[n], re = g_rowptr[n + 1];
    int h  = lane & 7;
    int eo = lane >> 3;
    float adv = g_ad[n * 8 + h];

    float m = -1e30f;
    for (int i = rs + eo; i < re; i += 4) {
        int s   = g_csrc[i];
        float l = g_as[s * 8 + h] + adv;
        l = l > 0.f ? l : 0.2f * l;
        m = fmaxf(m, l);
    }
    m = fmaxf(m, __shfl_xor_sync(0xffffffffu, m, 8));
    m = fmaxf(m, __shfl_xor_sync(0xffffffffu, m, 16));

    float den = 0.f;
    for (int i = rs + eo; i < re; i += 4) {
        int s   = g_csrc[i];
        float l = g_as[s * 8 + h] + adv;
        l = l > 0.f ? l : 0.2f * l;
        den += __expf(l - m);
    }
    den += __shfl_xor_sync(0xffffffffu, den, 8);
    den += __shfl_xor_sync(0xffffffffu, den, 16);
    float inv = 1.f / (den + 1e-16f);

    float acc[16];
#pragma unroll
    for (int i = 0; i < 16; i++) acc[i] = 0.f;
    int al_src0 = lane >> 3;
    int al_src1 = (lane + 32) >> 3;
    for (int i = rs; i < re; i++) {
        int s = g_csrc[i];
        float a8 = 0.f;
        if (lane < 8) {
            float l = g_as[s * 8 + lane] + adv;
            l  = l > 0.f ? l : 0.2f * l;
            a8 = __expf(l - m) * inv;
        }
        float al0 = __shfl_sync(0xffffffffu, a8, al_src0);
        float al1 = __shfl_sync(0xffffffffu, a8, al_src1);
        const uint4* hs = &g_hh4[(size_t)s * (HC / 8)];
        uint4 v0 = hs[lane];
        uint4 v1 = hs[lane + 32];
        float2 f;
        f = __half22float2(*(__half2*)&v0.x); acc[0] += al0 * f.x; acc[1] += al0 * f.y;
        f = __half22float2(*(__half2*)&v0.y); acc[2] += al0 * f.x; acc[3] += al0 * f.y;
        f = __half22float2(*(__half2*)&v0.z); acc[4] += al0 * f.x; acc[5] += al0 * f.y;
        f = __half22float2(*(__half2*)&v0.w); acc[6] += al0 * f.x; acc[7] += al0 * f.y;
        f = __half22float2(*(__half2*)&v1.x); acc[8]  += al1 * f.x; acc[9]  += al1 * f.y;
        f = __half22float2(*(__half2*)&v1.y); acc[10] += al1 * f.x; acc[11] += al1 * f.y;
        f = __half22float2(*(__half2*)&v1.z); acc[12] += al1 * f.x; acc[13] += al1 * f.y;
        f = __half22float2(*(__half2*)&v1.w); acc[14] += al1 * f.x; acc[15] += al1 * f.y;
    }

    if (elu) {
        __half* yh = (__half*)g_yh4 + (size_t)n * HC;
#pragma unroll
        for (int half = 0; half < 2; half++) {
            int cbase = half * 256 + 8 * lane;
            __half2 o4[4];
#pragma unroll
            for (int q = 0; q < 4; q++) {
                int c  = cbase + q * 2;
                float v0 = acc[half * 8 + q * 2 + 0] + bias[c];
                float v1 = acc[half * 8 + q * 2 + 1] + bias[c + 1];
                v0 = v0 > 0.f ? v0 : expm1f(v0);
                v1 = v1 > 0.f ? v1 : expm1f(v1);
                o4[q] = __floats2half2_rn(v0, v1);
            }
            *(uint4*)(yh + cbase) = *(uint4*)o4;
        }
    } else {
        float* yd = g_y + (size_t)n * HC;
#pragma unroll
        for (int half = 0; half < 2; half++) {
            int cbase = half * 256 + 8 * lane;
#pragma unroll
            for (int q = 0; q < 2; q++) {
                float4 o;
                o.x = acc[half * 8 + q * 4 + 0];
                o.y = acc[half * 8 + q * 4 + 1];
                o.z = acc[half * 8 + q * 4 + 2];
                o.w = acc[half * 8 + q * 4 + 3];
                *(float4*)(yd + cbase + q * 4) = o;
            }
        }
    }
}

// ---------------- head-mean + bias3 + output projection ----------------
__global__ void __launch_bounds__(64) final_kernel(const float* __restrict__ b3,
                                                   const float* __restrict__ Wo,
                                                   const float* __restrict__ bo,
                                                   float* __restrict__ out) {
    __shared__ float s[CH];
    int n = blockIdx.x, t = threadIdx.x;
    float acc = 0.f;
#pragma unroll
    for (int h = 0; h < HEADS; h++) acc += g_y[(size_t)n * HC + h * CH + t];
    s[t] = acc * 0.125f + b3[t];
    __syncthreads();
    if (t < OUTD) {
        float o = bo[t];
#pragma unroll
        for (int c = 0; c < CH; c++) o += s[c] * Wo[c * OUTD + t];
        out[n * OUTD + t] = o;
    }
}

// ---------------- launcher ----------------
extern "C" void kernel_launch(void* const* d_in, const int* in_sizes, int n_in,
                              void* d_out, int out_size) {
    const float* x     = (const float*)d_in[0];
    const void*  edges = d_in[1];
    const float* W1  = (const float*)d_in[2];
    const float* a1s = (const float*)d_in[3];
    const float* a1d = (const float*)d_in[4];
    const float* b1  = (const float*)d_in[5];
    const float* W2  = (const float*)d_in[6];
    const float* a2s = (const float*)d_in[7];
    const float* a2d = (const float*)d_in[8];
    const float* b2  = (const float*)d_in[9];
    const float* W3  = (const float*)d_in[10];
    const float* a3s = (const float*)d_in[11];
    const float* a3d = (const float*)d_in[12];
    const float* b3  = (const float*)d_in[13];
    const float* Wo  = (const float*)d_in[14];
    const float* bo  = (const float*)d_in[15];
    float* out = (float*)d_out;

    const int AGB = (N_NODES * 32 + 255) / 256;
    const dim3 GG(HC / 128, (N_NODES + 127) / 128);

    detect_dtype<<<1, 256>>>((const unsigned*)edges);
    zero_deg<<<NBLK, 256>>>();
    convert_edges<<<(E2 + 255) / 256, 256>>>(edges);
    scan_blocks<<<NBLK, 256>>>();
    scan_bsums<<<1, 256>>>();
    finalize_rowptr<<<NBLK, 256>>>();
    scatter_edges<<<(E2 + 255) / 256, 256>>>();

    // ---- layer 1 ----
    l1_gemm<<<(N_NODES + L1_NODES - 1) / L1_NODES, 256>>>(x, W1);
    alpha_kernel<<<N_NODES, 256>>>(a1s, a1d);
    aggregate_csr<<<AGB, 256>>>(b1, 1);

    // ---- layer 2 ----
    hgemm<<<GG, 256>>>(W2);
    alpha_kernel<<<N_NODES, 256>>>(a2s, a2d);
    aggregate_csr<<<AGB, 256>>>(b2, 1);

    // ---- layer 3 ----
    hgemm<<<GG, 256>>>(W3);
    alpha_kernel<<<N_NODES, 256>>>(a3s, a3d);
    aggregate_csr<<<AGB, 256>>>(b3, 0);

    final_kernel<<<N_NODES, 64>>>(b3, Wo, bo, out);
}